// round 1
// baseline (speedup 1.0000x reference)
#include <cuda_runtime.h>
#include <cuda_bf16.h>
#include <cstddef>

// Problem constants
#define N_NODES  100000
#define N_EDGES  400000
#define N_GRAPHS 4000
#define IN_DIM   128
#define HID      512
#define N_DESC   200
#define XDIM     (HID + N_DESC)   // 712
#define MLP1     500
#define MLP2     100
#define NCLS     2

// ---------------------------------------------------------------------------
// Device scratch (static __device__ arrays; allocation is forbidden)
// ---------------------------------------------------------------------------
__device__ int   g_deg[N_NODES];
__device__ int   g_off[N_NODES + 1];
__device__ int   g_cur[N_NODES];
__device__ int   g_csr[N_EDGES];

__device__ float g_agg0[(size_t)N_NODES * IN_DIM];   //  51 MB
__device__ float g_h1  [(size_t)N_NODES * HID];      // 205 MB
__device__ float g_agg1[(size_t)N_NODES * HID];      // 205 MB
__device__ float g_h2  [(size_t)N_NODES * HID];      // 205 MB
__device__ float g_X   [(size_t)N_GRAPHS * XDIM];
__device__ float g_m1  [(size_t)N_GRAPHS * MLP1];
__device__ float g_m2  [(size_t)N_GRAPHS * MLP2];

// ---------------------------------------------------------------------------
// CSR construction (dst-indexed in-edge lists)
// ---------------------------------------------------------------------------
__global__ void zero_deg_kernel() {
    int i = blockIdx.x * blockDim.x + threadIdx.x;
    if (i < N_NODES) g_deg[i] = 0;
}

__global__ void count_deg_kernel(const int* __restrict__ dst) {
    int e = blockIdx.x * blockDim.x + threadIdx.x;
    if (e < N_EDGES) atomicAdd(&g_deg[dst[e]], 1);
}

// Single-block exclusive scan of g_deg -> g_off (100001 entries).
__global__ void scan_deg_kernel() {
    __shared__ int part[1024];
    const int t  = threadIdx.x;
    const int CH = (N_NODES + 1023) / 1024;   // 98
    int start = t * CH;
    int end   = start + CH; if (end > N_NODES) end = N_NODES;
    if (start > N_NODES) start = N_NODES;

    int s = 0;
    for (int i = start; i < end; i++) s += g_deg[i];
    part[t] = s;
    __syncthreads();

    // Hillis-Steele inclusive scan over 1024 partials
    for (int off = 1; off < 1024; off <<= 1) {
        int v = (t >= off) ? part[t - off] : 0;
        __syncthreads();
        part[t] += v;
        __syncthreads();
    }
    int base = (t == 0) ? 0 : part[t - 1];
    int run = base;
    for (int i = start; i < end; i++) {
        g_off[i] = run;
        run += g_deg[i];
    }
    if (t == 1023) g_off[N_NODES] = part[1023];
}

__global__ void copy_cursor_kernel() {
    int i = blockIdx.x * blockDim.x + threadIdx.x;
    if (i < N_NODES) g_cur[i] = g_off[i];
}

__global__ void fill_csr_kernel(const int* __restrict__ src,
                                const int* __restrict__ dst) {
    int e = blockIdx.x * blockDim.x + threadIdx.x;
    if (e < N_EDGES) {
        int p = atomicAdd(&g_cur[dst[e]], 1);
        g_csr[p] = src[e];
    }
}

// ---------------------------------------------------------------------------
// Neighbor gather-sum:  out[n] = sum_{s in in(n)} feat[s]
// ---------------------------------------------------------------------------
__global__ void gather_sum_128(const float* __restrict__ feat,
                               float* __restrict__ out) {
    int n = blockIdx.x;
    int t = threadIdx.x;            // 128 threads, 1 float each
    int lo = g_off[n], hi = g_off[n + 1];
    float acc = 0.f;
    for (int j = lo; j < hi; j++) {
        int s = g_csr[j];
        acc += feat[(size_t)s * IN_DIM + t];
    }
    out[(size_t)n * IN_DIM + t] = acc;
}

__global__ void gather_sum_512(const float* __restrict__ h,
                               float* __restrict__ out) {
    int n = blockIdx.x;
    int t = threadIdx.x;            // 128 threads, float4 each
    int lo = g_off[n], hi = g_off[n + 1];
    float4 acc = make_float4(0.f, 0.f, 0.f, 0.f);
    for (int j = lo; j < hi; j++) {
        int s = g_csr[j];
        float4 v = reinterpret_cast<const float4*>(h + (size_t)s * HID)[t];
        acc.x += v.x; acc.y += v.y; acc.z += v.z; acc.w += v.w;
    }
    reinterpret_cast<float4*>(out + (size_t)n * HID)[t] = acc;
}

// ---------------------------------------------------------------------------
// SGEMM: C[M,N] = op(A[M,K] @ B[K,N] + bias), op = optional ReLU
// Classic 128x128x8 tiling, 8x8 per-thread microtile, 256 threads.
// ---------------------------------------------------------------------------
#define BM 128
#define BN 128
#define BK 8
#define TM 8
#define TN 8

__global__ __launch_bounds__(256)
void sgemm_bias_relu(const float* __restrict__ A, const float* __restrict__ B,
                     const float* __restrict__ bias, float* __restrict__ C,
                     int M, int N, int K, int relu) {
    __shared__ float As[BK][BM];
    __shared__ float Bs[BK][BN];
    const int tid  = threadIdx.x;
    const int row0 = blockIdx.y * BM;
    const int col0 = blockIdx.x * BN;
    const int tx = tid & 15;
    const int ty = tid >> 4;

    float acc[TM][TN];
    #pragma unroll
    for (int i = 0; i < TM; i++)
        #pragma unroll
        for (int j = 0; j < TN; j++) acc[i][j] = 0.f;

    for (int k0 = 0; k0 < K; k0 += BK) {
        // Load A tile (BM x BK) transposed into As[k][m]
        #pragma unroll
        for (int i = 0; i < 4; i++) {
            int idx = tid + i * 256;
            int m = idx >> 3, k = idx & 7;
            int gm = row0 + m, gk = k0 + k;
            As[k][m] = (gm < M && gk < K) ? A[(size_t)gm * K + gk] : 0.f;
        }
        // Load B tile (BK x BN)
        #pragma unroll
        for (int i = 0; i < 4; i++) {
            int idx = tid + i * 256;
            int k = idx >> 7, n = idx & 127;
            int gk = k0 + k, gn = col0 + n;
            Bs[k][n] = (gk < K && gn < N) ? B[(size_t)gk * N + gn] : 0.f;
        }
        __syncthreads();

        #pragma unroll
        for (int k = 0; k < BK; k++) {
            float a[TM], b[TN];
            #pragma unroll
            for (int i = 0; i < TM; i++) a[i] = As[k][ty * TM + i];
            #pragma unroll
            for (int j = 0; j < TN; j++) b[j] = Bs[k][tx * TN + j];
            #pragma unroll
            for (int i = 0; i < TM; i++)
                #pragma unroll
                for (int j = 0; j < TN; j++)
                    acc[i][j] += a[i] * b[j];
        }
        __syncthreads();
    }

    #pragma unroll
    for (int i = 0; i < TM; i++) {
        int gm = row0 + ty * TM + i;
        if (gm >= M) continue;
        #pragma unroll
        for (int j = 0; j < TN; j++) {
            int gn = col0 + tx * TN + j;
            if (gn >= N) continue;
            float v = acc[i][j] + (bias ? bias[gn] : 0.f);
            if (relu) v = fmaxf(v, 0.f);
            C[(size_t)gm * N + gn] = v;
        }
    }
}

// ---------------------------------------------------------------------------
// Per-graph mean pool over sorted node2graph + concat descriptors
// ---------------------------------------------------------------------------
__device__ __forceinline__ int lower_bound_dev(const int* a, int n, int v) {
    int lo = 0, hi = n;
    while (lo < hi) {
        int m = (lo + hi) >> 1;
        if (a[m] < v) lo = m + 1; else hi = m;
    }
    return lo;
}

__global__ void pool_concat_kernel(const float* __restrict__ h2,
                                   const float* __restrict__ desc,
                                   const int* __restrict__ n2g,
                                   float* __restrict__ X) {
    int g = blockIdx.x;
    __shared__ int s_lo, s_hi;
    if (threadIdx.x == 0) s_lo = lower_bound_dev(n2g, N_NODES, g);
    if (threadIdx.x == 1) s_hi = lower_bound_dev(n2g, N_NODES, g + 1);
    __syncthreads();
    int lo = s_lo, hi = s_hi;
    float inv = 1.f / fmaxf((float)(hi - lo), 1.f);

    int t = threadIdx.x;  // 128 threads, float4 over HID = 512
    float4 acc = make_float4(0.f, 0.f, 0.f, 0.f);
    for (int i = lo; i < hi; i++) {
        float4 v = reinterpret_cast<const float4*>(h2 + (size_t)i * HID)[t];
        acc.x += v.x; acc.y += v.y; acc.z += v.z; acc.w += v.w;
    }
    float* xrow = X + (size_t)g * XDIM;
    xrow[t * 4 + 0] = acc.x * inv;
    xrow[t * 4 + 1] = acc.y * inv;
    xrow[t * 4 + 2] = acc.z * inv;
    xrow[t * 4 + 3] = acc.w * inv;
    for (int d = t; d < N_DESC; d += 128)
        xrow[HID + d] = desc[(size_t)g * N_DESC + d];
}

// ---------------------------------------------------------------------------
// Tiny classifier: out[B,2] = m2[B,100] @ cw[100,2] + cb
// ---------------------------------------------------------------------------
__global__ void classifier_kernel(const float* __restrict__ m2,
                                  const float* __restrict__ cw,
                                  const float* __restrict__ cb,
                                  float* __restrict__ out) {
    int r = blockIdx.x * blockDim.x + threadIdx.x;
    if (r >= N_GRAPHS) return;
    float a0 = cb[0], a1 = cb[1];
    const float* row = m2 + (size_t)r * MLP2;
    #pragma unroll 4
    for (int k = 0; k < MLP2; k++) {
        float v = row[k];
        a0 += v * cw[k * 2 + 0];
        a1 += v * cw[k * 2 + 1];
    }
    out[r * 2 + 0] = a0;
    out[r * 2 + 1] = a1;
}

// ---------------------------------------------------------------------------
// Launch
// ---------------------------------------------------------------------------
extern "C" void kernel_launch(void* const* d_in, const int* in_sizes, int n_in,
                              void* d_out, int out_size) {
    const float* features    = (const float*)d_in[0];
    const float* descriptors = (const float*)d_in[1];
    const int*   src         = (const int*)  d_in[2];
    const int*   dst         = (const int*)  d_in[3];
    const int*   n2g         = (const int*)  d_in[4];
    const float* W1          = (const float*)d_in[5];
    const float* b1          = (const float*)d_in[6];
    const float* W2          = (const float*)d_in[7];
    const float* b2          = (const float*)d_in[8];
    const float* lw1         = (const float*)d_in[9];
    const float* lb1         = (const float*)d_in[10];
    const float* lw2         = (const float*)d_in[11];
    const float* lb2         = (const float*)d_in[12];
    const float* cw          = (const float*)d_in[13];
    const float* cb          = (const float*)d_in[14];
    float* out = (float*)d_out;

    float *agg0, *h1, *agg1, *h2, *X, *m1, *m2;
    cudaGetSymbolAddress((void**)&agg0, g_agg0);
    cudaGetSymbolAddress((void**)&h1,   g_h1);
    cudaGetSymbolAddress((void**)&agg1, g_agg1);
    cudaGetSymbolAddress((void**)&h2,   g_h2);
    cudaGetSymbolAddress((void**)&X,    g_X);
    cudaGetSymbolAddress((void**)&m1,   g_m1);
    cudaGetSymbolAddress((void**)&m2,   g_m2);

    // --- CSR build (per call; no caching allowed) ---
    zero_deg_kernel<<<(N_NODES + 255) / 256, 256>>>();
    count_deg_kernel<<<(N_EDGES + 255) / 256, 256>>>(dst);
    scan_deg_kernel<<<1, 1024>>>();
    copy_cursor_kernel<<<(N_NODES + 255) / 256, 256>>>();
    fill_csr_kernel<<<(N_EDGES + 255) / 256, 256>>>(src, dst);

    // --- Layer 1: aggregate-then-transform (A@X)@W1 ---
    gather_sum_128<<<N_NODES, 128>>>(features, agg0);
    {
        dim3 grid((HID + BN - 1) / BN, (N_NODES + BM - 1) / BM);
        sgemm_bias_relu<<<grid, 256>>>(agg0, W1, b1, h1,
                                       N_NODES, HID, IN_DIM, 1);
    }

    // --- Layer 2 ---
    gather_sum_512<<<N_NODES, 128>>>(h1, agg1);
    {
        dim3 grid((HID + BN - 1) / BN, (N_NODES + BM - 1) / BM);
        sgemm_bias_relu<<<grid, 256>>>(agg1, W2, b2, h2,
                                       N_NODES, HID, HID, 1);
    }

    // --- Mean pool + concat descriptors ---
    pool_concat_kernel<<<N_GRAPHS, 128>>>(h2, descriptors, n2g, X);

    // --- MLP head ---
    {
        dim3 grid((MLP1 + BN - 1) / BN, (N_GRAPHS + BM - 1) / BM);
        sgemm_bias_relu<<<grid, 256>>>(X, lw1, lb1, m1,
                                       N_GRAPHS, MLP1, XDIM, 1);
    }
    {
        dim3 grid((MLP2 + BN - 1) / BN, (N_GRAPHS + BM - 1) / BM);
        sgemm_bias_relu<<<grid, 256>>>(m1, lw2, lb2, m2,
                                       N_GRAPHS, MLP2, MLP1, 1);
    }
    classifier_kernel<<<(N_GRAPHS + 127) / 128, 128>>>(m2, cw, cb, out);
}

// round 3
// speedup vs baseline: 2.9806x; 2.9806x over previous
#include <cuda_runtime.h>
#include <cuda_bf16.h>
#include <cstdint>
#include <cstddef>

// Problem constants
#define N_NODES  100000
#define N_EDGES  400000
#define N_GRAPHS 4000
#define IN_DIM   128
#define HID      512
#define N_DESC   200
#define XDIM     (HID + N_DESC)   // 712
#define XPAD     736              // padded to multiple of 32
#define MLP1     500
#define MLP1PAD  512
#define MLP2     100

// ===========================================================================
// PTX helpers (all plain sm_80-era features; no sm_103a-gated instructions)
// ===========================================================================
__device__ __forceinline__ uint32_t smem_to_u32(const void* p) {
    uint32_t a;
    asm("{ .reg .u64 t; cvta.to.shared.u64 t, %1; cvt.u32.u64 %0, t; }"
        : "=r"(a) : "l"(p));
    return a;
}

__device__ __forceinline__ void ldsm_x4(uint32_t& r0, uint32_t& r1,
                                        uint32_t& r2, uint32_t& r3,
                                        uint32_t addr) {
    asm volatile("ldmatrix.sync.aligned.m8n8.x4.shared.b16 {%0,%1,%2,%3}, [%4];"
                 : "=r"(r0), "=r"(r1), "=r"(r2), "=r"(r3) : "r"(addr));
}

__device__ __forceinline__ void mma_bf16(float* c, const uint32_t* a,
                                         uint32_t b0, uint32_t b1) {
    asm volatile(
        "mma.sync.aligned.m16n8k16.row.col.f32.bf16.bf16.f32 "
        "{%0,%1,%2,%3}, {%4,%5,%6,%7}, {%8,%9}, {%0,%1,%2,%3};"
        : "+f"(c[0]), "+f"(c[1]), "+f"(c[2]), "+f"(c[3])
        : "r"(a[0]), "r"(a[1]), "r"(a[2]), "r"(a[3]), "r"(b0), "r"(b1));
}

__device__ __forceinline__ void cpa16(uint32_t s, const void* g, uint32_t sz) {
    asm volatile("cp.async.cg.shared.global [%0], [%1], 16, %2;"
                 :: "r"(s), "l"(g), "r"(sz));
}
#define CP_COMMIT() asm volatile("cp.async.commit_group;" ::: "memory")
#define CP_WAIT(n)  asm volatile("cp.async.wait_group %0;" :: "n"(n) : "memory")

// ===========================================================================
// Device scratch
// ===========================================================================
__device__ int g_deg[N_NODES];
__device__ int g_off[N_NODES + 1];
__device__ int g_cur[N_NODES];
__device__ int g_csr[N_EDGES];

__device__ __nv_bfloat16 g_a0hi[(size_t)N_NODES * IN_DIM];
__device__ __nv_bfloat16 g_a0lo[(size_t)N_NODES * IN_DIM];
__device__ __nv_bfloat16 g_a1hi[(size_t)N_NODES * HID];
__device__ __nv_bfloat16 g_a1lo[(size_t)N_NODES * HID];
__device__ float         g_h1  [(size_t)N_NODES * HID];
__device__ float         g_h2  [(size_t)N_NODES * HID];
__device__ __nv_bfloat16 g_Xhi [(size_t)N_GRAPHS * XPAD];
__device__ __nv_bfloat16 g_Xlo [(size_t)N_GRAPHS * XPAD];
__device__ float         g_m1  [(size_t)N_GRAPHS * MLP1];
__device__ float         g_m2  [(size_t)N_GRAPHS * MLP2];

// Weight images: B^T bf16 hi/lo, [Npad][Kpad], k-contiguous
__device__ __nv_bfloat16 g_B1hi[512 * 128],      g_B1lo[512 * 128];
__device__ __nv_bfloat16 g_B2hi[512 * 512],      g_B2lo[512 * 512];
__device__ __nv_bfloat16 g_BLhi[MLP1PAD * XPAD], g_BLlo[MLP1PAD * XPAD];

// ===========================================================================
// Weight prep: W[K_real,N_real] -> B^T hi/lo [Npad][Kpad] bf16 (zero padded)
// ===========================================================================
__global__ void prep_B(const float* __restrict__ W, __nv_bfloat16* __restrict__ Bhi,
                       __nv_bfloat16* __restrict__ Blo,
                       int K_real, int N_real, int Kpad, int Npad) {
    int idx = blockIdx.x * blockDim.x + threadIdx.x;
    if (idx >= Npad * Kpad) return;
    int n = idx / Kpad, k = idx % Kpad;
    float v = (k < K_real && n < N_real) ? W[(size_t)k * N_real + n] : 0.f;
    __nv_bfloat16 h = __float2bfloat16(v);
    __nv_bfloat16 l = __float2bfloat16(v - __bfloat162float(h));
    Bhi[idx] = h;
    Blo[idx] = l;
}

// ===========================================================================
// CSR construction
// ===========================================================================
__global__ void zero_deg_kernel() {
    int i = blockIdx.x * blockDim.x + threadIdx.x;
    if (i < N_NODES) g_deg[i] = 0;
}
__global__ void count_deg_kernel(const int* __restrict__ dst) {
    int e = blockIdx.x * blockDim.x + threadIdx.x;
    if (e < N_EDGES) atomicAdd(&g_deg[dst[e]], 1);
}
__global__ void scan_deg_kernel() {
    __shared__ int part[1024];
    const int t  = threadIdx.x;
    const int CH = (N_NODES + 1023) / 1024;
    int start = t * CH;
    int end   = start + CH; if (end > N_NODES) end = N_NODES;
    if (start > N_NODES) start = N_NODES;
    int s = 0;
    for (int i = start; i < end; i++) s += g_deg[i];
    part[t] = s;
    __syncthreads();
    for (int off = 1; off < 1024; off <<= 1) {
        int v = (t >= off) ? part[t - off] : 0;
        __syncthreads();
        part[t] += v;
        __syncthreads();
    }
    int run = (t == 0) ? 0 : part[t - 1];
    for (int i = start; i < end; i++) { g_off[i] = run; run += g_deg[i]; }
    if (t == 1023) g_off[N_NODES] = part[1023];
}
__global__ void copy_cursor_kernel() {
    int i = blockIdx.x * blockDim.x + threadIdx.x;
    if (i < N_NODES) g_cur[i] = g_off[i];
}
__global__ void fill_csr_kernel(const int* __restrict__ src,
                                const int* __restrict__ dst) {
    int e = blockIdx.x * blockDim.x + threadIdx.x;
    if (e < N_EDGES) {
        int p = atomicAdd(&g_cur[dst[e]], 1);
        g_csr[p] = src[e];
    }
}

// ===========================================================================
// Gather-sum kernels (emit bf16 hi/lo split directly)
// ===========================================================================
__global__ void gather_sum_128(const float* __restrict__ feat,
                               __nv_bfloat16* __restrict__ ohi,
                               __nv_bfloat16* __restrict__ olo) {
    int n = blockIdx.x;
    int t = threadIdx.x;            // 128 threads
    int lo = g_off[n], hi = g_off[n + 1];
    float acc = 0.f;
    for (int j = lo; j < hi; j++)
        acc += feat[(size_t)g_csr[j] * IN_DIM + t];
    __nv_bfloat16 h = __float2bfloat16(acc);
    __nv_bfloat16 l = __float2bfloat16(acc - __bfloat162float(h));
    ohi[(size_t)n * IN_DIM + t] = h;
    olo[(size_t)n * IN_DIM + t] = l;
}

__global__ void gather_sum_512(const float* __restrict__ h,
                               __nv_bfloat16* __restrict__ ohi,
                               __nv_bfloat16* __restrict__ olo) {
    int n = blockIdx.x;
    int t = threadIdx.x;            // 128 threads, 4 floats each
    int lo = g_off[n], hi = g_off[n + 1];
    float4 acc = make_float4(0.f, 0.f, 0.f, 0.f);
    for (int j = lo; j < hi; j++) {
        float4 v = reinterpret_cast<const float4*>(h + (size_t)g_csr[j] * HID)[t];
        acc.x += v.x; acc.y += v.y; acc.z += v.z; acc.w += v.w;
    }
    size_t base = (size_t)n * HID + t * 4;
    float a[4] = {acc.x, acc.y, acc.z, acc.w};
    #pragma unroll
    for (int i = 0; i < 4; i++) {
        __nv_bfloat16 hh = __float2bfloat16(a[i]);
        __nv_bfloat16 ll = __float2bfloat16(a[i] - __bfloat162float(hh));
        ohi[base + i] = hh;
        olo[base + i] = ll;
    }
}

// ===========================================================================
// bf16-split tensor-core GEMM: C[M,Nreal] = relu(A@W + bias)
// CTA tile 128x128, BK=32, 8 warps (32m x 64n each), cp.async double buffer.
// A given as bf16 hi/lo [M][K]; B as bf16 hi/lo [Npad][K] (n-major).
// SMEM rows padded to 40 bf16 (80B) -> conflict-free ldmatrix.
// ===========================================================================
#define GSTRIDE 40          // bf16 elements per smem row
#define GTILE   10240u      // 128 * 80 bytes
#define GBUF    40960u      // 4 tiles (Ahi,Alo,Bhi,Blo)
#define GDSM    (2 * GBUF)

__global__ __launch_bounds__(256, 2)
void gemm_bf16x3(const __nv_bfloat16* __restrict__ Ahi,
                 const __nv_bfloat16* __restrict__ Alo,
                 const __nv_bfloat16* __restrict__ Bhi,
                 const __nv_bfloat16* __restrict__ Blo,
                 const float* __restrict__ bias, float* __restrict__ C,
                 int M, int Nreal, int K)
{
    extern __shared__ char dsm[];
    const uint32_t sbase = smem_to_u32(dsm);
    const int tid  = threadIdx.x;
    const int lane = tid & 31;
    const int wid  = tid >> 5;
    const int row0 = blockIdx.y * 128;
    const int col0 = blockIdx.x * 128;
    const int NC   = K / 32;

    const int m_base = (wid & 3) * 32;
    const int n_base = (wid >> 2) * 64;

    float acc[2][8][4];
    #pragma unroll
    for (int i = 0; i < 2; i++)
        #pragma unroll
        for (int j = 0; j < 8; j++)
            #pragma unroll
            for (int q = 0; q < 4; q++) acc[i][j][q] = 0.f;

    // ---- async loader for one 32-k chunk into buffer `buf` ----
    auto load_chunk = [&](int buf, int c) {
        uint32_t s = sbase + (uint32_t)buf * GBUF;
        #pragma unroll
        for (int i = 0; i < 2; i++) {
            int f  = tid + i * 256;        // 0..511
            int m  = f >> 2, k8 = f & 3;   // k8: 16B unit within 64B row
            int gm = row0 + m;
            uint32_t ok = (gm < M) ? 16u : 0u;
            int gmc = (gm < M) ? gm : 0;
            size_t goff = (size_t)gmc * K + c * 32 + k8 * 8;
            uint32_t d = s + m * 80 + k8 * 16;
            cpa16(d,          Ahi + goff, ok);
            cpa16(d + GTILE,  Alo + goff, ok);
        }
        #pragma unroll
        for (int i = 0; i < 2; i++) {
            int f = tid + i * 256;
            int n = f >> 2, k8 = f & 3;
            size_t goff = (size_t)(col0 + n) * K + c * 32 + k8 * 8;
            uint32_t d = s + 2 * GTILE + n * 80 + k8 * 16;
            cpa16(d,          Bhi + goff, 16u);
            cpa16(d + GTILE,  Blo + goff, 16u);
        }
        CP_COMMIT();
    };

    load_chunk(0, 0);

    for (int c = 0; c < NC; c++) {
        const int buf = c & 1;
        if (c + 1 < NC) {
            load_chunk(buf ^ 1, c + 1);
            CP_WAIT(1);
        } else {
            CP_WAIT(0);
        }
        __syncthreads();

        const uint32_t sA = sbase + (uint32_t)buf * GBUF;
        const uint32_t sB = sA + 2 * GTILE;

        #pragma unroll
        for (int ks = 0; ks < 2; ks++) {
            uint32_t ah[2][4], al[2][4];
            #pragma unroll
            for (int im = 0; im < 2; im++) {
                uint32_t ra = sA + (uint32_t)(m_base + im * 16 + (lane & 15)) * 80
                                 + (uint32_t)(ks * 16 + ((lane >> 4) * 8)) * 2;
                ldsm_x4(ah[im][0], ah[im][1], ah[im][2], ah[im][3], ra);
                ldsm_x4(al[im][0], al[im][1], al[im][2], al[im][3], ra + GTILE);
            }
            #pragma unroll
            for (int g = 0; g < 4; g++) {
                uint32_t bh[4], bl[4];
                uint32_t rb = sB + (uint32_t)(n_base + g * 16 +
                                   ((lane >> 4) & 1) * 8 + (lane & 7)) * 80
                                 + (uint32_t)(ks * 16 + ((lane >> 3) & 1) * 8) * 2;
                ldsm_x4(bh[0], bh[1], bh[2], bh[3], rb);
                ldsm_x4(bl[0], bl[1], bl[2], bl[3], rb + GTILE);
                #pragma unroll
                for (int im = 0; im < 2; im++) {
                    #pragma unroll
                    for (int sub = 0; sub < 2; sub++) {
                        float* cc = acc[im][g * 2 + sub];
                        mma_bf16(cc, ah[im], bh[sub * 2], bh[sub * 2 + 1]);
                        mma_bf16(cc, ah[im], bl[sub * 2], bl[sub * 2 + 1]);
                        mma_bf16(cc, al[im], bh[sub * 2], bh[sub * 2 + 1]);
                    }
                }
            }
        }
        __syncthreads();
    }

    // ---- epilogue: bias + relu + store ----
    const bool full_n = (col0 + 128 <= Nreal);
    #pragma unroll
    for (int im = 0; im < 2; im++) {
        int m0 = row0 + m_base + im * 16 + (lane >> 2);
        #pragma unroll
        for (int j = 0; j < 8; j++) {
            int n = col0 + n_base + j * 8 + (lane & 3) * 2;
            if (full_n) {
                float b0 = bias[n], b1 = bias[n + 1];
                if (m0 < M) {
                    float2 v;
                    v.x = fmaxf(acc[im][j][0] + b0, 0.f);
                    v.y = fmaxf(acc[im][j][1] + b1, 0.f);
                    *reinterpret_cast<float2*>(C + (size_t)m0 * Nreal + n) = v;
                }
                if (m0 + 8 < M) {
                    float2 v;
                    v.x = fmaxf(acc[im][j][2] + b0, 0.f);
                    v.y = fmaxf(acc[im][j][3] + b1, 0.f);
                    *reinterpret_cast<float2*>(C + (size_t)(m0 + 8) * Nreal + n) = v;
                }
            } else {
                #pragma unroll
                for (int q = 0; q < 4; q++) {
                    int mm = m0 + (q >> 1) * 8;
                    int nn = n + (q & 1);
                    if (mm < M && nn < Nreal)
                        C[(size_t)mm * Nreal + nn] =
                            fmaxf(acc[im][j][q] + bias[nn], 0.f);
                }
            }
        }
    }
}

// ===========================================================================
// FFMA SGEMM (small MLP2 layer only)
// ===========================================================================
#define BM 128
#define BN 128
#define BK 8
#define TM 8
#define TN 8
__global__ __launch_bounds__(256)
void sgemm_bias_relu(const float* __restrict__ A, const float* __restrict__ B,
                     const float* __restrict__ bias, float* __restrict__ C,
                     int M, int N, int K, int relu) {
    __shared__ float As[BK][BM];
    __shared__ float Bs[BK][BN];
    const int tid  = threadIdx.x;
    const int row0 = blockIdx.y * BM;
    const int col0 = blockIdx.x * BN;
    const int tx = tid & 15;
    const int ty = tid >> 4;
    float acc[TM][TN];
    #pragma unroll
    for (int i = 0; i < TM; i++)
        #pragma unroll
        for (int j = 0; j < TN; j++) acc[i][j] = 0.f;
    for (int k0 = 0; k0 < K; k0 += BK) {
        #pragma unroll
        for (int i = 0; i < 4; i++) {
            int idx = tid + i * 256;
            int m = idx >> 3, k = idx & 7;
            int gm = row0 + m, gk = k0 + k;
            As[k][m] = (gm < M && gk < K) ? A[(size_t)gm * K + gk] : 0.f;
        }
        #pragma unroll
        for (int i = 0; i < 4; i++) {
            int idx = tid + i * 256;
            int k = idx >> 7, n = idx & 127;
            int gk = k0 + k, gn = col0 + n;
            Bs[k][n] = (gk < K && gn < N) ? B[(size_t)gk * N + gn] : 0.f;
        }
        __syncthreads();
        #pragma unroll
        for (int k = 0; k < BK; k++) {
            float a[TM], b[TN];
            #pragma unroll
            for (int i = 0; i < TM; i++) a[i] = As[k][ty * TM + i];
            #pragma unroll
            for (int j = 0; j < TN; j++) b[j] = Bs[k][tx * TN + j];
            #pragma unroll
            for (int i = 0; i < TM; i++)
                #pragma unroll
                for (int j = 0; j < TN; j++)
                    acc[i][j] += a[i] * b[j];
        }
        __syncthreads();
    }
    #pragma unroll
    for (int i = 0; i < TM; i++) {
        int gm = row0 + ty * TM + i;
        if (gm >= M) continue;
        #pragma unroll
        for (int j = 0; j < TN; j++) {
            int gn = col0 + tx * TN + j;
            if (gn >= N) continue;
            float v = acc[i][j] + (bias ? bias[gn] : 0.f);
            if (relu) v = fmaxf(v, 0.f);
            C[(size_t)gm * N + gn] = v;
        }
    }
}

// ===========================================================================
// Mean pool (sorted node2graph) + concat descriptors -> Xhi/Xlo (padded)
// ===========================================================================
__device__ __forceinline__ int lower_bound_dev(const int* a, int n, int v) {
    int lo = 0, hi = n;
    while (lo < hi) {
        int m = (lo + hi) >> 1;
        if (a[m] < v) lo = m + 1; else hi = m;
    }
    return lo;
}
__global__ void pool_concat_kernel(const float* __restrict__ h2,
                                   const float* __restrict__ desc,
                                   const int* __restrict__ n2g,
                                   __nv_bfloat16* __restrict__ Xhi,
                                   __nv_bfloat16* __restrict__ Xlo) {
    int g = blockIdx.x;
    __shared__ int s_lo, s_hi;
    if (threadIdx.x == 0) s_lo = lower_bound_dev(n2g, N_NODES, g);
    if (threadIdx.x == 1) s_hi = lower_bound_dev(n2g, N_NODES, g + 1);
    __syncthreads();
    int lo = s_lo, hi = s_hi;
    float inv = 1.f / fmaxf((float)(hi - lo), 1.f);
    int t = threadIdx.x;   // 128 threads
    float4 acc = make_float4(0.f, 0.f, 0.f, 0.f);
    for (int i = lo; i < hi; i++) {
        float4 v = reinterpret_cast<const float4*>(h2 + (size_t)i * HID)[t];
        acc.x += v.x; acc.y += v.y; acc.z += v.z; acc.w += v.w;
    }
    size_t rb = (size_t)g * XPAD;
    float a[4] = {acc.x * inv, acc.y * inv, acc.z * inv, acc.w * inv};
    #pragma unroll
    for (int i = 0; i < 4; i++) {
        __nv_bfloat16 h = __float2bfloat16(a[i]);
        __nv_bfloat16 l = __float2bfloat16(a[i] - __bfloat162float(h));
        Xhi[rb + t * 4 + i] = h;
        Xlo[rb + t * 4 + i] = l;
    }
    for (int d = t; d < N_DESC; d += 128) {
        float v = desc[(size_t)g * N_DESC + d];
        __nv_bfloat16 h = __float2bfloat16(v);
        __nv_bfloat16 l = __float2bfloat16(v - __bfloat162float(h));
        Xhi[rb + HID + d] = h;
        Xlo[rb + HID + d] = l;
    }
    for (int d = t; d < XPAD - XDIM; d += 128) {
        Xhi[rb + XDIM + d] = __float2bfloat16(0.f);
        Xlo[rb + XDIM + d] = __float2bfloat16(0.f);
    }
}

// ===========================================================================
// Tiny classifier
// ===========================================================================
__global__ void classifier_kernel(const float* __restrict__ m2,
                                  const float* __restrict__ cw,
                                  const float* __restrict__ cb,
                                  float* __restrict__ out) {
    int r = blockIdx.x * blockDim.x + threadIdx.x;
    if (r >= N_GRAPHS) return;
    float a0 = cb[0], a1 = cb[1];
    const float* row = m2 + (size_t)r * MLP2;
    #pragma unroll 4
    for (int k = 0; k < MLP2; k++) {
        float v = row[k];
        a0 += v * cw[k * 2 + 0];
        a1 += v * cw[k * 2 + 1];
    }
    out[r * 2 + 0] = a0;
    out[r * 2 + 1] = a1;
}

// ===========================================================================
// Launch
// ===========================================================================
extern "C" void kernel_launch(void* const* d_in, const int* in_sizes, int n_in,
                              void* d_out, int out_size) {
    const float* features    = (const float*)d_in[0];
    const float* descriptors = (const float*)d_in[1];
    const int*   src         = (const int*)  d_in[2];
    const int*   dst         = (const int*)  d_in[3];
    const int*   n2g         = (const int*)  d_in[4];
    const float* W1          = (const float*)d_in[5];
    const float* b1          = (const float*)d_in[6];
    const float* W2          = (const float*)d_in[7];
    const float* b2          = (const float*)d_in[8];
    const float* lw1         = (const float*)d_in[9];
    const float* lb1         = (const float*)d_in[10];
    const float* lw2         = (const float*)d_in[11];
    const float* lb2         = (const float*)d_in[12];
    const float* cw          = (const float*)d_in[13];
    const float* cb          = (const float*)d_in[14];
    float* out = (float*)d_out;

    __nv_bfloat16 *a0hi, *a0lo, *a1hi, *a1lo, *Xhi, *Xlo;
    __nv_bfloat16 *B1hi, *B1lo, *B2hi, *B2lo, *BLhi, *BLlo;
    float *h1, *h2, *m1, *m2;
    cudaGetSymbolAddress((void**)&a0hi, g_a0hi);
    cudaGetSymbolAddress((void**)&a0lo, g_a0lo);
    cudaGetSymbolAddress((void**)&a1hi, g_a1hi);
    cudaGetSymbolAddress((void**)&a1lo, g_a1lo);
    cudaGetSymbolAddress((void**)&h1,   g_h1);
    cudaGetSymbolAddress((void**)&h2,   g_h2);
    cudaGetSymbolAddress((void**)&Xhi,  g_Xhi);
    cudaGetSymbolAddress((void**)&Xlo,  g_Xlo);
    cudaGetSymbolAddress((void**)&m1,   g_m1);
    cudaGetSymbolAddress((void**)&m2,   g_m2);
    cudaGetSymbolAddress((void**)&B1hi, g_B1hi);
    cudaGetSymbolAddress((void**)&B1lo, g_B1lo);
    cudaGetSymbolAddress((void**)&B2hi, g_B2hi);
    cudaGetSymbolAddress((void**)&B2lo, g_B2lo);
    cudaGetSymbolAddress((void**)&BLhi, g_BLhi);
    cudaGetSymbolAddress((void**)&BLlo, g_BLlo);

    cudaFuncSetAttribute(gemm_bf16x3,
                         cudaFuncAttributeMaxDynamicSharedMemorySize, GDSM);

    // --- Weight prep ---
    prep_B<<<(512 * 128 + 255) / 256, 256>>>(W1, B1hi, B1lo, IN_DIM, HID, 128, 512);
    prep_B<<<(512 * 512 + 255) / 256, 256>>>(W2, B2hi, B2lo, HID, HID, 512, 512);
    prep_B<<<(MLP1PAD * XPAD + 255) / 256, 256>>>(lw1, BLhi, BLlo, XDIM, MLP1,
                                                  XPAD, MLP1PAD);

    // --- CSR build ---
    zero_deg_kernel<<<(N_NODES + 255) / 256, 256>>>();
    count_deg_kernel<<<(N_EDGES + 255) / 256, 256>>>(dst);
    scan_deg_kernel<<<1, 1024>>>();
    copy_cursor_kernel<<<(N_NODES + 255) / 256, 256>>>();
    fill_csr_kernel<<<(N_EDGES + 255) / 256, 256>>>(src, dst);

    // --- Layer 1: h1 = relu((A@X)@W1 + b1) ---
    gather_sum_128<<<N_NODES, 128>>>(features, a0hi, a0lo);
    { dim3 g(4, (N_NODES + 127) / 128);
      gemm_bf16x3<<<g, 256, GDSM>>>(a0hi, a0lo, B1hi, B1lo, b1, h1,
                                    N_NODES, HID, IN_DIM); }

    // --- Layer 2 ---
    gather_sum_512<<<N_NODES, 128>>>(h1, a1hi, a1lo);
    { dim3 g(4, (N_NODES + 127) / 128);
      gemm_bf16x3<<<g, 256, GDSM>>>(a1hi, a1lo, B2hi, B2lo, b2, h2,
                                    N_NODES, HID, HID); }

    // --- Mean pool + concat ---
    pool_concat_kernel<<<N_GRAPHS, 128>>>(h2, descriptors, n2g, Xhi, Xlo);

    // --- MLP head ---
    { dim3 g(4, (N_GRAPHS + 127) / 128);
      gemm_bf16x3<<<g, 256, GDSM>>>(Xhi, Xlo, BLhi, BLlo, lb1, m1,
                                    N_GRAPHS, MLP1, XPAD); }
    { dim3 g(1, (N_GRAPHS + 127) / 128);
      sgemm_bias_relu<<<g, 256>>>(m1, lw2, lb2, m2, N_GRAPHS, MLP2, MLP1, 1); }
    classifier_kernel<<<(N_GRAPHS + 127) / 128, 128>>>(m2, cw, cb, out);
}

// round 4
// speedup vs baseline: 3.1078x; 1.0427x over previous
#include <cuda_runtime.h>
#include <cuda_fp16.h>
#include <cstdint>
#include <cstddef>

// Problem constants
#define N_NODES  100000
#define N_EDGES  400000
#define N_GRAPHS 4000
#define IN_DIM   128
#define HID      512
#define N_DESC   200
#define XDIM     (HID + N_DESC)   // 712
#define XPAD     736              // multiple of 32
#define MLP1     500
#define MLP1PAD  512
#define MLP2     100

// ===========================================================================
// PTX helpers (plain sm_80-era features only)
// ===========================================================================
__device__ __forceinline__ uint32_t smem_to_u32(const void* p) {
    uint32_t a;
    asm("{ .reg .u64 t; cvta.to.shared.u64 t, %1; cvt.u32.u64 %0, t; }"
        : "=r"(a) : "l"(p));
    return a;
}
__device__ __forceinline__ void ldsm_x4(uint32_t& r0, uint32_t& r1,
                                        uint32_t& r2, uint32_t& r3,
                                        uint32_t addr) {
    asm volatile("ldmatrix.sync.aligned.m8n8.x4.shared.b16 {%0,%1,%2,%3}, [%4];"
                 : "=r"(r0), "=r"(r1), "=r"(r2), "=r"(r3) : "r"(addr));
}
__device__ __forceinline__ void mma_fp16(float* c, const uint32_t* a,
                                         uint32_t b0, uint32_t b1) {
    asm volatile(
        "mma.sync.aligned.m16n8k16.row.col.f32.f16.f16.f32 "
        "{%0,%1,%2,%3}, {%4,%5,%6,%7}, {%8,%9}, {%0,%1,%2,%3};"
        : "+f"(c[0]), "+f"(c[1]), "+f"(c[2]), "+f"(c[3])
        : "r"(a[0]), "r"(a[1]), "r"(a[2]), "r"(a[3]), "r"(b0), "r"(b1));
}
__device__ __forceinline__ void cpa16(uint32_t s, const void* g, uint32_t sz) {
    asm volatile("cp.async.cg.shared.global [%0], [%1], 16, %2;"
                 :: "r"(s), "l"(g), "r"(sz));
}
#define CP_COMMIT() asm volatile("cp.async.commit_group;" ::: "memory")
#define CP_WAIT(n)  asm volatile("cp.async.wait_group %0;" :: "n"(n) : "memory")

// ===========================================================================
// Device scratch
// ===========================================================================
__device__ int g_deg[N_NODES];
__device__ int g_off[N_NODES + 1];
__device__ int g_cur[N_NODES];
__device__ int g_csr[N_EDGES];

__device__ __half g_a0 [(size_t)N_NODES * IN_DIM];
__device__ __half g_h1 [(size_t)N_NODES * HID];
__device__ __half g_a1 [(size_t)N_NODES * HID];
__device__ __half g_h2 [(size_t)N_NODES * HID];
__device__ __half g_X  [(size_t)N_GRAPHS * XPAD];
__device__ float  g_m1 [(size_t)N_GRAPHS * MLP1];
__device__ float  g_m2 [(size_t)N_GRAPHS * MLP2];

// Weight images: B^T fp16 hi/lo, [Npad][Kpad], k-contiguous
__device__ __half g_B1hi[512 * 128],      g_B1lo[512 * 128];
__device__ __half g_B2hi[512 * 512],      g_B2lo[512 * 512];
__device__ __half g_BLhi[MLP1PAD * XPAD], g_BLlo[MLP1PAD * XPAD];

// ===========================================================================
// Weight prep: W[K_real,N_real] -> B^T hi/lo [Npad][Kpad] fp16 (zero padded)
// ===========================================================================
__global__ void prep_B(const float* __restrict__ W, __half* __restrict__ Bhi,
                       __half* __restrict__ Blo,
                       int K_real, int N_real, int Kpad, int Npad) {
    int idx = blockIdx.x * blockDim.x + threadIdx.x;
    if (idx >= Npad * Kpad) return;
    int n = idx / Kpad, k = idx % Kpad;
    float v = (k < K_real && n < N_real) ? W[(size_t)k * N_real + n] : 0.f;
    __half h = __float2half_rn(v);
    __half l = __float2half_rn(v - __half2float(h));
    Bhi[idx] = h;
    Blo[idx] = l;
}

// ===========================================================================
// CSR construction
// ===========================================================================
__global__ void zero_deg_kernel() {
    int i = blockIdx.x * blockDim.x + threadIdx.x;
    if (i < N_NODES) g_deg[i] = 0;
}
__global__ void count_deg_kernel(const int* __restrict__ dst) {
    int e = blockIdx.x * blockDim.x + threadIdx.x;
    if (e < N_EDGES) atomicAdd(&g_deg[dst[e]], 1);
}
// scan + cursor init fused
__global__ void scan_deg_kernel() {
    __shared__ int part[1024];
    const int t  = threadIdx.x;
    const int CH = (N_NODES + 1023) / 1024;
    int start = t * CH;
    int end   = start + CH; if (end > N_NODES) end = N_NODES;
    if (start > N_NODES) start = N_NODES;
    int s = 0;
    for (int i = start; i < end; i++) s += g_deg[i];
    part[t] = s;
    __syncthreads();
    for (int off = 1; off < 1024; off <<= 1) {
        int v = (t >= off) ? part[t - off] : 0;
        __syncthreads();
        part[t] += v;
        __syncthreads();
    }
    int run = (t == 0) ? 0 : part[t - 1];
    for (int i = start; i < end; i++) {
        g_off[i] = run;
        g_cur[i] = run;
        run += g_deg[i];
    }
    if (t == 1023) g_off[N_NODES] = part[1023];
}
__global__ void fill_csr_kernel(const int* __restrict__ src,
                                const int* __restrict__ dst) {
    int e = blockIdx.x * blockDim.x + threadIdx.x;
    if (e < N_EDGES) {
        int p = atomicAdd(&g_cur[dst[e]], 1);
        g_csr[p] = src[e];
    }
}

// ===========================================================================
// Gather-sum kernels
// ===========================================================================
__global__ void gather_sum_128(const float* __restrict__ feat,
                               __half* __restrict__ o) {
    int n = blockIdx.x;
    int t = threadIdx.x;            // 128 threads, 1 col each
    int lo = g_off[n], hi = g_off[n + 1];
    float acc = 0.f;
    for (int j = lo; j < hi; j++)
        acc += feat[(size_t)g_csr[j] * IN_DIM + t];
    o[(size_t)n * IN_DIM + t] = __float2half_rn(acc);
}

// h (fp16) rows of 512; 128 threads x 4 values (2x half2 = 8B per thread)
__global__ void gather_sum_512h(const __half* __restrict__ h,
                                __half* __restrict__ o) {
    int n = blockIdx.x;
    int t = threadIdx.x;
    int lo = g_off[n], hi = g_off[n + 1];
    float2 a0 = make_float2(0.f, 0.f), a1 = make_float2(0.f, 0.f);
    for (int j = lo; j < hi; j++) {
        const __half2* row = reinterpret_cast<const __half2*>(
            h + (size_t)g_csr[j] * HID);
        float2 v0 = __half22float2(row[t * 2 + 0]);
        float2 v1 = __half22float2(row[t * 2 + 1]);
        a0.x += v0.x; a0.y += v0.y;
        a1.x += v1.x; a1.y += v1.y;
    }
    __half2* orow = reinterpret_cast<__half2*>(o + (size_t)n * HID);
    orow[t * 2 + 0] = __floats2half2_rn(a0.x, a0.y);
    orow[t * 2 + 1] = __floats2half2_rn(a1.x, a1.y);
}

// ===========================================================================
// fp16 tensor-core GEMM, A single / B hi+lo split (2 MMA passes):
//   C[M,Nreal] = relu(A@W + bias)
// CTA tile 128m x 256n, BK=32, 8 warps (32m x 128n each), cp.async dbl-buffer.
// SMEM rows padded to 80B -> conflict-free ldmatrix.
// ===========================================================================
#define ATILE 10240u        // 128 rows * 80B
#define BTILE 20480u        // 256 rows * 80B
#define GBUF  51200u        // A + Bhi + Blo
#define GDSM  (2 * GBUF)

template <bool HALF_OUT>
__global__ __launch_bounds__(256, 1)
void gemm_fp16_bsplit(const __half* __restrict__ A,
                      const __half* __restrict__ Bhi,
                      const __half* __restrict__ Blo,
                      const float* __restrict__ bias, void* __restrict__ Cout,
                      int M, int Nreal, int K)
{
    extern __shared__ char dsm[];
    const uint32_t sbase = smem_to_u32(dsm);
    const int tid  = threadIdx.x;
    const int lane = tid & 31;
    const int wid  = tid >> 5;
    const int row0 = blockIdx.y * 128;
    const int col0 = blockIdx.x * 256;
    const int NC   = K / 32;

    const int m_base = (wid & 3) * 32;
    const int n_base = (wid >> 2) * 128;

    float acc[2][16][4];
    #pragma unroll
    for (int i = 0; i < 2; i++)
        #pragma unroll
        for (int j = 0; j < 16; j++)
            #pragma unroll
            for (int q = 0; q < 4; q++) acc[i][j][q] = 0.f;

    auto load_chunk = [&](int buf, int c) {
        uint32_t s = sbase + (uint32_t)buf * GBUF;
        // A: 128 rows x 4x16B units -> 512 units, 2 per thread
        #pragma unroll
        for (int i = 0; i < 2; i++) {
            int f  = tid + i * 256;
            int m  = f >> 2, k8 = f & 3;
            int gm = row0 + m;
            uint32_t ok = (gm < M) ? 16u : 0u;
            int gmc = (gm < M) ? gm : 0;
            cpa16(s + m * 80 + k8 * 16, A + (size_t)gmc * K + c * 32 + k8 * 8, ok);
        }
        // B: 256 rows x 4 units x {hi,lo} -> 2048 units, 8 per thread
        #pragma unroll
        for (int i = 0; i < 4; i++) {
            int f = tid + i * 256;
            int n = f >> 2, k8 = f & 3;
            size_t goff = (size_t)(col0 + n) * K + c * 32 + k8 * 8;
            uint32_t d = s + ATILE + n * 80 + k8 * 16;
            cpa16(d,         Bhi + goff, 16u);
            cpa16(d + BTILE, Blo + goff, 16u);
        }
        CP_COMMIT();
    };

    load_chunk(0, 0);

    for (int c = 0; c < NC; c++) {
        const int buf = c & 1;
        if (c + 1 < NC) {
            load_chunk(buf ^ 1, c + 1);
            CP_WAIT(1);
        } else {
            CP_WAIT(0);
        }
        __syncthreads();

        const uint32_t sA  = sbase + (uint32_t)buf * GBUF;
        const uint32_t sBh = sA + ATILE;

        #pragma unroll
        for (int ks = 0; ks < 2; ks++) {
            uint32_t a[2][4];
            #pragma unroll
            for (int im = 0; im < 2; im++) {
                uint32_t ra = sA + (uint32_t)(m_base + im * 16 + (lane & 15)) * 80
                                 + (uint32_t)(ks * 16 + ((lane >> 4) * 8)) * 2;
                ldsm_x4(a[im][0], a[im][1], a[im][2], a[im][3], ra);
            }
            #pragma unroll
            for (int g = 0; g < 8; g++) {
                uint32_t bh[4], bl[4];
                uint32_t rb = sBh + (uint32_t)(n_base + g * 16 +
                                   ((lane >> 4) & 1) * 8 + (lane & 7)) * 80
                                 + (uint32_t)(ks * 16 + ((lane >> 3) & 1) * 8) * 2;
                ldsm_x4(bh[0], bh[1], bh[2], bh[3], rb);
                ldsm_x4(bl[0], bl[1], bl[2], bl[3], rb + BTILE);
                #pragma unroll
                for (int im = 0; im < 2; im++) {
                    #pragma unroll
                    for (int sub = 0; sub < 2; sub++) {
                        float* cc = acc[im][g * 2 + sub];
                        mma_fp16(cc, a[im], bh[sub * 2], bh[sub * 2 + 1]);
                        mma_fp16(cc, a[im], bl[sub * 2], bl[sub * 2 + 1]);
                    }
                }
            }
        }
        __syncthreads();
    }

    // ---- epilogue: bias + relu + store (fp16 or fp32) ----
    const bool full_n = (col0 + 256 <= Nreal);
    #pragma unroll
    for (int im = 0; im < 2; im++) {
        int m0 = row0 + m_base + im * 16 + (lane >> 2);
        #pragma unroll
        for (int j = 0; j < 16; j++) {
            int n = col0 + n_base + j * 8 + (lane & 3) * 2;
            if (full_n) {
                float b0 = bias[n], b1 = bias[n + 1];
                #pragma unroll
                for (int half_row = 0; half_row < 2; half_row++) {
                    int mm = m0 + half_row * 8;
                    if (mm >= M) continue;
                    float v0 = fmaxf(acc[im][j][half_row * 2 + 0] + b0, 0.f);
                    float v1 = fmaxf(acc[im][j][half_row * 2 + 1] + b1, 0.f);
                    if (HALF_OUT) {
                        __half2* p = reinterpret_cast<__half2*>(
                            (__half*)Cout + (size_t)mm * Nreal + n);
                        *p = __floats2half2_rn(v0, v1);
                    } else {
                        float2* p = reinterpret_cast<float2*>(
                            (float*)Cout + (size_t)mm * Nreal + n);
                        *p = make_float2(v0, v1);
                    }
                }
            } else {
                #pragma unroll
                for (int q = 0; q < 4; q++) {
                    int mm = m0 + (q >> 1) * 8;
                    int nn = n + (q & 1);
                    if (mm < M && nn < Nreal) {
                        float v = fmaxf(acc[im][j][q] + bias[nn], 0.f);
                        if (HALF_OUT)
                            ((__half*)Cout)[(size_t)mm * Nreal + nn] =
                                __float2half_rn(v);
                        else
                            ((float*)Cout)[(size_t)mm * Nreal + nn] = v;
                    }
                }
            }
        }
    }
}

// ===========================================================================
// FFMA SGEMM (small MLP2 layer only, fp32)
// ===========================================================================
#define BM 128
#define BN 128
#define BK 8
#define TM 8
#define TN 8
__global__ __launch_bounds__(256)
void sgemm_bias_relu(const float* __restrict__ A, const float* __restrict__ B,
                     const float* __restrict__ bias, float* __restrict__ C,
                     int M, int N, int K, int relu) {
    __shared__ float As[BK][BM];
    __shared__ float Bs[BK][BN];
    const int tid  = threadIdx.x;
    const int row0 = blockIdx.y * BM;
    const int col0 = blockIdx.x * BN;
    const int tx = tid & 15;
    const int ty = tid >> 4;
    float acc[TM][TN];
    #pragma unroll
    for (int i = 0; i < TM; i++)
        #pragma unroll
        for (int j = 0; j < TN; j++) acc[i][j] = 0.f;
    for (int k0 = 0; k0 < K; k0 += BK) {
        #pragma unroll
        for (int i = 0; i < 4; i++) {
            int idx = tid + i * 256;
            int m = idx >> 3, k = idx & 7;
            int gm = row0 + m, gk = k0 + k;
            As[k][m] = (gm < M && gk < K) ? A[(size_t)gm * K + gk] : 0.f;
        }
        #pragma unroll
        for (int i = 0; i < 4; i++) {
            int idx = tid + i * 256;
            int k = idx >> 7, n = idx & 127;
            int gk = k0 + k, gn = col0 + n;
            Bs[k][n] = (gk < K && gn < N) ? B[(size_t)gk * N + gn] : 0.f;
        }
        __syncthreads();
        #pragma unroll
        for (int k = 0; k < BK; k++) {
            float a[TM], b[TN];
            #pragma unroll
            for (int i = 0; i < TM; i++) a[i] = As[k][ty * TM + i];
            #pragma unroll
            for (int j = 0; j < TN; j++) b[j] = Bs[k][tx * TN + j];
            #pragma unroll
            for (int i = 0; i < TM; i++)
                #pragma unroll
                for (int j = 0; j < TN; j++)
                    acc[i][j] += a[i] * b[j];
        }
        __syncthreads();
    }
    #pragma unroll
    for (int i = 0; i < TM; i++) {
        int gm = row0 + ty * TM + i;
        if (gm >= M) continue;
        #pragma unroll
        for (int j = 0; j < TN; j++) {
            int gn = col0 + tx * TN + j;
            if (gn >= N) continue;
            float v = acc[i][j] + (bias ? bias[gn] : 0.f);
            if (relu) v = fmaxf(v, 0.f);
            C[(size_t)gm * N + gn] = v;
        }
    }
}

// ===========================================================================
// Mean pool (sorted node2graph, fp16 input) + concat descriptors -> X fp16
// ===========================================================================
__device__ __forceinline__ int lower_bound_dev(const int* a, int n, int v) {
    int lo = 0, hi = n;
    while (lo < hi) {
        int m = (lo + hi) >> 1;
        if (a[m] < v) lo = m + 1; else hi = m;
    }
    return lo;
}
__global__ void pool_concat_kernel(const __half* __restrict__ h2,
                                   const float* __restrict__ desc,
                                   const int* __restrict__ n2g,
                                   __half* __restrict__ X) {
    int g = blockIdx.x;
    __shared__ int s_lo, s_hi;
    if (threadIdx.x == 0) s_lo = lower_bound_dev(n2g, N_NODES, g);
    if (threadIdx.x == 1) s_hi = lower_bound_dev(n2g, N_NODES, g + 1);
    __syncthreads();
    int lo = s_lo, hi = s_hi;
    float inv = 1.f / fmaxf((float)(hi - lo), 1.f);
    int t = threadIdx.x;   // 128 threads x 4 values
    float2 a0 = make_float2(0.f, 0.f), a1 = make_float2(0.f, 0.f);
    for (int i = lo; i < hi; i++) {
        const __half2* row = reinterpret_cast<const __half2*>(
            h2 + (size_t)i * HID);
        float2 v0 = __half22float2(row[t * 2 + 0]);
        float2 v1 = __half22float2(row[t * 2 + 1]);
        a0.x += v0.x; a0.y += v0.y;
        a1.x += v1.x; a1.y += v1.y;
    }
    size_t rb = (size_t)g * XPAD;
    __half2* xrow = reinterpret_cast<__half2*>(X + rb);
    xrow[t * 2 + 0] = __floats2half2_rn(a0.x * inv, a0.y * inv);
    xrow[t * 2 + 1] = __floats2half2_rn(a1.x * inv, a1.y * inv);
    for (int d = t; d < N_DESC; d += 128)
        X[rb + HID + d] = __float2half_rn(desc[(size_t)g * N_DESC + d]);
    for (int d = t; d < XPAD - XDIM; d += 128)
        X[rb + XDIM + d] = __float2half_rn(0.f);
}

// ===========================================================================
// Tiny classifier
// ===========================================================================
__global__ void classifier_kernel(const float* __restrict__ m2,
                                  const float* __restrict__ cw,
                                  const float* __restrict__ cb,
                                  float* __restrict__ out) {
    int r = blockIdx.x * blockDim.x + threadIdx.x;
    if (r >= N_GRAPHS) return;
    float a0 = cb[0], a1 = cb[1];
    const float* row = m2 + (size_t)r * MLP2;
    #pragma unroll 4
    for (int k = 0; k < MLP2; k++) {
        float v = row[k];
        a0 += v * cw[k * 2 + 0];
        a1 += v * cw[k * 2 + 1];
    }
    out[r * 2 + 0] = a0;
    out[r * 2 + 1] = a1;
}

// ===========================================================================
// Launch
// ===========================================================================
extern "C" void kernel_launch(void* const* d_in, const int* in_sizes, int n_in,
                              void* d_out, int out_size) {
    const float* features    = (const float*)d_in[0];
    const float* descriptors = (const float*)d_in[1];
    const int*   src         = (const int*)  d_in[2];
    const int*   dst         = (const int*)  d_in[3];
    const int*   n2g         = (const int*)  d_in[4];
    const float* W1          = (const float*)d_in[5];
    const float* b1          = (const float*)d_in[6];
    const float* W2          = (const float*)d_in[7];
    const float* b2          = (const float*)d_in[8];
    const float* lw1         = (const float*)d_in[9];
    const float* lb1         = (const float*)d_in[10];
    const float* lw2         = (const float*)d_in[11];
    const float* lb2         = (const float*)d_in[12];
    const float* cw          = (const float*)d_in[13];
    const float* cb          = (const float*)d_in[14];
    float* out = (float*)d_out;

    __half *a0, *h1, *a1, *h2, *X;
    __half *B1hi, *B1lo, *B2hi, *B2lo, *BLhi, *BLlo;
    float *m1, *m2;
    cudaGetSymbolAddress((void**)&a0,   g_a0);
    cudaGetSymbolAddress((void**)&h1,   g_h1);
    cudaGetSymbolAddress((void**)&a1,   g_a1);
    cudaGetSymbolAddress((void**)&h2,   g_h2);
    cudaGetSymbolAddress((void**)&X,    g_X);
    cudaGetSymbolAddress((void**)&m1,   g_m1);
    cudaGetSymbolAddress((void**)&m2,   g_m2);
    cudaGetSymbolAddress((void**)&B1hi, g_B1hi);
    cudaGetSymbolAddress((void**)&B1lo, g_B1lo);
    cudaGetSymbolAddress((void**)&B2hi, g_B2hi);
    cudaGetSymbolAddress((void**)&B2lo, g_B2lo);
    cudaGetSymbolAddress((void**)&BLhi, g_BLhi);
    cudaGetSymbolAddress((void**)&BLlo, g_BLlo);

    cudaFuncSetAttribute(gemm_fp16_bsplit<true>,
                         cudaFuncAttributeMaxDynamicSharedMemorySize, GDSM);
    cudaFuncSetAttribute(gemm_fp16_bsplit<false>,
                         cudaFuncAttributeMaxDynamicSharedMemorySize, GDSM);

    // --- Weight prep ---
    prep_B<<<(512 * 128 + 255) / 256, 256>>>(W1, B1hi, B1lo, IN_DIM, HID, 128, 512);
    prep_B<<<(512 * 512 + 255) / 256, 256>>>(W2, B2hi, B2lo, HID, HID, 512, 512);
    prep_B<<<(MLP1PAD * XPAD + 255) / 256, 256>>>(lw1, BLhi, BLlo, XDIM, MLP1,
                                                  XPAD, MLP1PAD);

    // --- CSR build ---
    zero_deg_kernel<<<(N_NODES + 255) / 256, 256>>>();
    count_deg_kernel<<<(N_EDGES + 255) / 256, 256>>>(dst);
    scan_deg_kernel<<<1, 1024>>>();
    fill_csr_kernel<<<(N_EDGES + 255) / 256, 256>>>(src, dst);

    // --- Layer 1: h1 = relu((A@X)@W1 + b1) ---
    gather_sum_128<<<N_NODES, 128>>>(features, a0);
    { dim3 g(2, (N_NODES + 127) / 128);
      gemm_fp16_bsplit<true><<<g, 256, GDSM>>>(a0, B1hi, B1lo, b1, h1,
                                               N_NODES, HID, IN_DIM); }

    // --- Layer 2 ---
    gather_sum_512h<<<N_NODES, 128>>>(h1, a1);
    { dim3 g(2, (N_NODES + 127) / 128);
      gemm_fp16_bsplit<true><<<g, 256, GDSM>>>(a1, B2hi, B2lo, b2, h2,
                                               N_NODES, HID, HID); }

    // --- Mean pool + concat ---
    pool_concat_kernel<<<N_GRAPHS, 128>>>(h2, descriptors, n2g, X);

    // --- MLP head ---
    { dim3 g(2, (N_GRAPHS + 127) / 128);
      gemm_fp16_bsplit<false><<<g, 256, GDSM>>>(X, BLhi, BLlo, lb1, m1,
                                                N_GRAPHS, MLP1, XPAD); }
    { dim3 g(1, (N_GRAPHS + 127) / 128);
      sgemm_bias_relu<<<g, 256>>>(m1, lw2, lb2, m2, N_GRAPHS, MLP2, MLP1, 1); }
    classifier_kernel<<<(N_GRAPHS + 127) / 128, 128>>>(m2, cw, cb, out);
}

// round 5
// speedup vs baseline: 3.4508x; 1.1104x over previous
#include <cuda_runtime.h>
#include <cuda_fp16.h>
#include <cstdint>
#include <cstddef>

// Problem constants
#define N_NODES  100000
#define N_EDGES  400000
#define N_GRAPHS 4000
#define IN_DIM   128
#define HID      512
#define N_DESC   200
#define XDIM     (HID + N_DESC)   // 712
#define XPAD     736              // multiple of 32
#define MLP1     500
#define MLP1PAD  512
#define MLP2     100

// ===========================================================================
// PTX helpers (plain sm_80-era features only)
// ===========================================================================
__device__ __forceinline__ uint32_t smem_to_u32(const void* p) {
    uint32_t a;
    asm("{ .reg .u64 t; cvta.to.shared.u64 t, %1; cvt.u32.u64 %0, t; }"
        : "=r"(a) : "l"(p));
    return a;
}
__device__ __forceinline__ void ldsm_x4(uint32_t& r0, uint32_t& r1,
                                        uint32_t& r2, uint32_t& r3,
                                        uint32_t addr) {
    asm volatile("ldmatrix.sync.aligned.m8n8.x4.shared.b16 {%0,%1,%2,%3}, [%4];"
                 : "=r"(r0), "=r"(r1), "=r"(r2), "=r"(r3) : "r"(addr));
}
__device__ __forceinline__ void mma_fp16(float* c, const uint32_t* a,
                                         uint32_t b0, uint32_t b1) {
    asm volatile(
        "mma.sync.aligned.m16n8k16.row.col.f32.f16.f16.f32 "
        "{%0,%1,%2,%3}, {%4,%5,%6,%7}, {%8,%9}, {%0,%1,%2,%3};"
        : "+f"(c[0]), "+f"(c[1]), "+f"(c[2]), "+f"(c[3])
        : "r"(a[0]), "r"(a[1]), "r"(a[2]), "r"(a[3]), "r"(b0), "r"(b1));
}
__device__ __forceinline__ void cpa16(uint32_t s, const void* g, uint32_t sz) {
    asm volatile("cp.async.cg.shared.global [%0], [%1], 16, %2;"
                 :: "r"(s), "l"(g), "r"(sz));
}
#define CP_COMMIT() asm volatile("cp.async.commit_group;" ::: "memory")
#define CP_WAIT(n)  asm volatile("cp.async.wait_group %0;" :: "n"(n) : "memory")

// ===========================================================================
// Device scratch (16B aligned for int4 access)
// ===========================================================================
__device__ __align__(16) int g_deg[N_NODES];
__device__ __align__(16) int g_off[N_NODES + 4];
__device__ __align__(16) int g_cur[N_NODES];
__device__ int g_csr[N_EDGES];

__device__ __half g_a0 [(size_t)N_NODES * IN_DIM];
__device__ __half g_h1 [(size_t)N_NODES * HID];
__device__ __half g_a1 [(size_t)N_NODES * HID];
__device__ __half g_h2 [(size_t)N_NODES * HID];
__device__ __half g_X  [(size_t)N_GRAPHS * XPAD];
__device__ float  g_m1 [(size_t)N_GRAPHS * MLP1];
__device__ float  g_m2 [(size_t)N_GRAPHS * MLP2];

// Weight images: B^T fp16 hi/lo, [Npad][Kpad], k-contiguous
__device__ __half g_B1hi[512 * 128],      g_B1lo[512 * 128];
__device__ __half g_B2hi[512 * 512],      g_B2lo[512 * 512];
__device__ __half g_BLhi[MLP1PAD * XPAD], g_BLlo[MLP1PAD * XPAD];

// ===========================================================================
// Fused init: zero g_deg + prep all three weight images (one launch)
// ===========================================================================
#define Z0 (N_NODES)                 // zero g_deg
#define Z1 (512 * 128)               // B1
#define Z2 (512 * 512)               // B2
#define Z3 (MLP1PAD * XPAD)          // BL
#define INIT_TOTAL (Z0 + Z1 + Z2 + Z3)

__device__ __forceinline__ void prep_one(const float* __restrict__ W,
                                         __half* __restrict__ Bhi,
                                         __half* __restrict__ Blo,
                                         int local, int K_real, int N_real,
                                         int Kpad) {
    int n = local / Kpad, k = local % Kpad;
    float v = (k < K_real && n < N_real) ? W[(size_t)k * N_real + n] : 0.f;
    __half h = __float2half_rn(v);
    __half l = __float2half_rn(v - __half2float(h));
    Bhi[local] = h;
    Blo[local] = l;
}

__global__ void init_kernel(const float* __restrict__ W1,
                            const float* __restrict__ W2,
                            const float* __restrict__ lw1,
                            __half* __restrict__ B1hi, __half* __restrict__ B1lo,
                            __half* __restrict__ B2hi, __half* __restrict__ B2lo,
                            __half* __restrict__ BLhi, __half* __restrict__ BLlo) {
    int idx = blockIdx.x * blockDim.x + threadIdx.x;
    if (idx < Z0) {
        g_deg[idx] = 0;
    } else if (idx < Z0 + Z1) {
        prep_one(W1, B1hi, B1lo, idx - Z0, IN_DIM, HID, 128);
    } else if (idx < Z0 + Z1 + Z2) {
        prep_one(W2, B2hi, B2lo, idx - Z0 - Z1, HID, HID, 512);
    } else if (idx < INIT_TOTAL) {
        prep_one(lw1, BLhi, BLlo, idx - Z0 - Z1 - Z2, XDIM, MLP1, XPAD);
    }
}

// ===========================================================================
// CSR construction
// ===========================================================================
__global__ void count_deg_kernel(const int* __restrict__ dst) {
    int e = blockIdx.x * blockDim.x + threadIdx.x;
    if (e < N_EDGES) atomicAdd(&g_deg[dst[e]], 1);
}

// Single-block scan, int4 loads/stores, fused cursor init.
// 1000 active threads x 100 elements (25 int4) each.
__global__ void scan_deg_kernel() {
    __shared__ int part[1024];
    const int t = threadIdx.x;
    int s = 0;
    if (t < 1000) {
        const int4* p = reinterpret_cast<const int4*>(g_deg + t * 100);
        #pragma unroll
        for (int i = 0; i < 25; i++) {
            int4 v = p[i];
            s += v.x + v.y + v.z + v.w;
        }
    }
    part[t] = s;
    __syncthreads();
    for (int off = 1; off < 1024; off <<= 1) {
        int v = (t >= off) ? part[t - off] : 0;
        __syncthreads();
        part[t] += v;
        __syncthreads();
    }
    int run = (t == 0) ? 0 : part[t - 1];
    if (t < 1000) {
        const int4* p = reinterpret_cast<const int4*>(g_deg + t * 100);
        int4* o  = reinterpret_cast<int4*>(g_off + t * 100);
        int4* cu = reinterpret_cast<int4*>(g_cur + t * 100);
        #pragma unroll
        for (int i = 0; i < 25; i++) {
            int4 d = p[i];
            int4 w;
            w.x = run; run += d.x;
            w.y = run; run += d.y;
            w.z = run; run += d.z;
            w.w = run; run += d.w;
            o[i]  = w;
            cu[i] = w;
        }
    }
    if (t == 1023) g_off[N_NODES] = part[1023];
}

__global__ void fill_csr_kernel(const int* __restrict__ src,
                                const int* __restrict__ dst) {
    int e = blockIdx.x * blockDim.x + threadIdx.x;
    if (e < N_EDGES) {
        int p = atomicAdd(&g_cur[dst[e]], 1);
        g_csr[p] = src[e];
    }
}

// ===========================================================================
// Gather-sum kernels (2 nodes per 256-thread block)
// ===========================================================================
__global__ __launch_bounds__(256)
void gather_sum_128(const float* __restrict__ feat, __half* __restrict__ o) {
    int n = blockIdx.x * 2 + (threadIdx.x >> 7);
    int t = threadIdx.x & 127;
    int lo = g_off[n], hi = g_off[n + 1];
    float acc = 0.f;
    for (int j = lo; j < hi; j++)
        acc += feat[(size_t)g_csr[j] * IN_DIM + t];
    o[(size_t)n * IN_DIM + t] = __float2half_rn(acc);
}

__global__ __launch_bounds__(256)
void gather_sum_512h(const __half* __restrict__ h, __half* __restrict__ o) {
    int n = blockIdx.x * 2 + (threadIdx.x >> 7);
    int t = threadIdx.x & 127;
    int lo = g_off[n], hi = g_off[n + 1];
    float2 a0 = make_float2(0.f, 0.f), a1 = make_float2(0.f, 0.f);
    for (int j = lo; j < hi; j++) {
        const __half2* row = reinterpret_cast<const __half2*>(
            h + (size_t)g_csr[j] * HID);
        float2 v0 = __half22float2(row[t * 2 + 0]);
        float2 v1 = __half22float2(row[t * 2 + 1]);
        a0.x += v0.x; a0.y += v0.y;
        a1.x += v1.x; a1.y += v1.y;
    }
    __half2* orow = reinterpret_cast<__half2*>(o + (size_t)n * HID);
    orow[t * 2 + 0] = __floats2half2_rn(a0.x, a0.y);
    orow[t * 2 + 1] = __floats2half2_rn(a1.x, a1.y);
}

// ===========================================================================
// fp16 tensor-core GEMM, A single / B hi+lo split (2 MMA passes):
//   C[M,Nreal] = relu(A@W + bias)
// CTA tile 128m x 256n, BK=32, 8 warps (32m x 128n each), cp.async dbl-buffer.
// ===========================================================================
#define ATILE 10240u        // 128 rows * 80B
#define BTILE 20480u        // 256 rows * 80B
#define GBUF  51200u        // A + Bhi + Blo
#define GDSM  (2 * GBUF)

template <bool HALF_OUT>
__global__ __launch_bounds__(256, 1)
void gemm_fp16_bsplit(const __half* __restrict__ A,
                      const __half* __restrict__ Bhi,
                      const __half* __restrict__ Blo,
                      const float* __restrict__ bias, void* __restrict__ Cout,
                      int M, int Nreal, int K)
{
    extern __shared__ char dsm[];
    const uint32_t sbase = smem_to_u32(dsm);
    const int tid  = threadIdx.x;
    const int lane = tid & 31;
    const int wid  = tid >> 5;
    const int row0 = blockIdx.y * 128;
    const int col0 = blockIdx.x * 256;
    const int NC   = K / 32;

    const int m_base = (wid & 3) * 32;
    const int n_base = (wid >> 2) * 128;

    float acc[2][16][4];
    #pragma unroll
    for (int i = 0; i < 2; i++)
        #pragma unroll
        for (int j = 0; j < 16; j++)
            #pragma unroll
            for (int q = 0; q < 4; q++) acc[i][j][q] = 0.f;

    auto load_chunk = [&](int buf, int c) {
        uint32_t s = sbase + (uint32_t)buf * GBUF;
        #pragma unroll
        for (int i = 0; i < 2; i++) {
            int f  = tid + i * 256;
            int m  = f >> 2, k8 = f & 3;
            int gm = row0 + m;
            uint32_t ok = (gm < M) ? 16u : 0u;
            int gmc = (gm < M) ? gm : 0;
            cpa16(s + m * 80 + k8 * 16, A + (size_t)gmc * K + c * 32 + k8 * 8, ok);
        }
        #pragma unroll
        for (int i = 0; i < 4; i++) {
            int f = tid + i * 256;
            int n = f >> 2, k8 = f & 3;
            size_t goff = (size_t)(col0 + n) * K + c * 32 + k8 * 8;
            uint32_t d = s + ATILE + n * 80 + k8 * 16;
            cpa16(d,         Bhi + goff, 16u);
            cpa16(d + BTILE, Blo + goff, 16u);
        }
        CP_COMMIT();
    };

    load_chunk(0, 0);

    for (int c = 0; c < NC; c++) {
        const int buf = c & 1;
        if (c + 1 < NC) {
            load_chunk(buf ^ 1, c + 1);
            CP_WAIT(1);
        } else {
            CP_WAIT(0);
        }
        __syncthreads();

        const uint32_t sA  = sbase + (uint32_t)buf * GBUF;
        const uint32_t sBh = sA + ATILE;

        #pragma unroll
        for (int ks = 0; ks < 2; ks++) {
            uint32_t a[2][4];
            #pragma unroll
            for (int im = 0; im < 2; im++) {
                uint32_t ra = sA + (uint32_t)(m_base + im * 16 + (lane & 15)) * 80
                                 + (uint32_t)(ks * 16 + ((lane >> 4) * 8)) * 2;
                ldsm_x4(a[im][0], a[im][1], a[im][2], a[im][3], ra);
            }
            #pragma unroll
            for (int g = 0; g < 8; g++) {
                uint32_t bh[4], bl[4];
                uint32_t rb = sBh + (uint32_t)(n_base + g * 16 +
                                   ((lane >> 4) & 1) * 8 + (lane & 7)) * 80
                                 + (uint32_t)(ks * 16 + ((lane >> 3) & 1) * 8) * 2;
                ldsm_x4(bh[0], bh[1], bh[2], bh[3], rb);
                ldsm_x4(bl[0], bl[1], bl[2], bl[3], rb + BTILE);
                #pragma unroll
                for (int im = 0; im < 2; im++) {
                    #pragma unroll
                    for (int sub = 0; sub < 2; sub++) {
                        float* cc = acc[im][g * 2 + sub];
                        mma_fp16(cc, a[im], bh[sub * 2], bh[sub * 2 + 1]);
                        mma_fp16(cc, a[im], bl[sub * 2], bl[sub * 2 + 1]);
                    }
                }
            }
        }
        __syncthreads();
    }

    // ---- epilogue: bias + relu + store ----
    const bool full_n = (col0 + 256 <= Nreal);
    #pragma unroll
    for (int im = 0; im < 2; im++) {
        int m0 = row0 + m_base + im * 16 + (lane >> 2);
        #pragma unroll
        for (int j = 0; j < 16; j++) {
            int n = col0 + n_base + j * 8 + (lane & 3) * 2;
            if (full_n) {
                float b0 = bias[n], b1 = bias[n + 1];
                #pragma unroll
                for (int hr = 0; hr < 2; hr++) {
                    int mm = m0 + hr * 8;
                    if (mm >= M) continue;
                    float v0 = fmaxf(acc[im][j][hr * 2 + 0] + b0, 0.f);
                    float v1 = fmaxf(acc[im][j][hr * 2 + 1] + b1, 0.f);
                    if (HALF_OUT) {
                        *reinterpret_cast<__half2*>(
                            (__half*)Cout + (size_t)mm * Nreal + n) =
                            __floats2half2_rn(v0, v1);
                    } else {
                        *reinterpret_cast<float2*>(
                            (float*)Cout + (size_t)mm * Nreal + n) =
                            make_float2(v0, v1);
                    }
                }
            } else {
                #pragma unroll
                for (int q = 0; q < 4; q++) {
                    int mm = m0 + (q >> 1) * 8;
                    int nn = n + (q & 1);
                    if (mm < M && nn < Nreal) {
                        float v = fmaxf(acc[im][j][q] + bias[nn], 0.f);
                        if (HALF_OUT)
                            ((__half*)Cout)[(size_t)mm * Nreal + nn] =
                                __float2half_rn(v);
                        else
                            ((float*)Cout)[(size_t)mm * Nreal + nn] = v;
                    }
                }
            }
        }
    }
}

// ===========================================================================
// FFMA SGEMM (small MLP2 layer only, fp32)
// ===========================================================================
#define BM 128
#define BN 128
#define BK 8
#define TM 8
#define TN 8
__global__ __launch_bounds__(256)
void sgemm_bias_relu(const float* __restrict__ A, const float* __restrict__ B,
                     const float* __restrict__ bias, float* __restrict__ C,
                     int M, int N, int K, int relu) {
    __shared__ float As[BK][BM];
    __shared__ float Bs[BK][BN];
    const int tid  = threadIdx.x;
    const int row0 = blockIdx.y * BM;
    const int col0 = blockIdx.x * BN;
    const int tx = tid & 15;
    const int ty = tid >> 4;
    float acc[TM][TN];
    #pragma unroll
    for (int i = 0; i < TM; i++)
        #pragma unroll
        for (int j = 0; j < TN; j++) acc[i][j] = 0.f;
    for (int k0 = 0; k0 < K; k0 += BK) {
        #pragma unroll
        for (int i = 0; i < 4; i++) {
            int idx = tid + i * 256;
            int m = idx >> 3, k = idx & 7;
            int gm = row0 + m, gk = k0 + k;
            As[k][m] = (gm < M && gk < K) ? A[(size_t)gm * K + gk] : 0.f;
        }
        #pragma unroll
        for (int i = 0; i < 4; i++) {
            int idx = tid + i * 256;
            int k = idx >> 7, n = idx & 127;
            int gk = k0 + k, gn = col0 + n;
            Bs[k][n] = (gk < K && gn < N) ? B[(size_t)gk * N + gn] : 0.f;
        }
        __syncthreads();
        #pragma unroll
        for (int k = 0; k < BK; k++) {
            float a[TM], b[TN];
            #pragma unroll
            for (int i = 0; i < TM; i++) a[i] = As[k][ty * TM + i];
            #pragma unroll
            for (int j = 0; j < TN; j++) b[j] = Bs[k][tx * TN + j];
            #pragma unroll
            for (int i = 0; i < TM; i++)
                #pragma unroll
                for (int j = 0; j < TN; j++)
                    acc[i][j] += a[i] * b[j];
        }
        __syncthreads();
    }
    #pragma unroll
    for (int i = 0; i < TM; i++) {
        int gm = row0 + ty * TM + i;
        if (gm >= M) continue;
        #pragma unroll
        for (int j = 0; j < TN; j++) {
            int gn = col0 + tx * TN + j;
            if (gn >= N) continue;
            float v = acc[i][j] + (bias ? bias[gn] : 0.f);
            if (relu) v = fmaxf(v, 0.f);
            C[(size_t)gm * N + gn] = v;
        }
    }
}

// ===========================================================================
// Mean pool (sorted node2graph, fp16 input) + concat descriptors -> X fp16
// ===========================================================================
__device__ __forceinline__ int lower_bound_dev(const int* a, int n, int v) {
    int lo = 0, hi = n;
    while (lo < hi) {
        int m = (lo + hi) >> 1;
        if (a[m] < v) lo = m + 1; else hi = m;
    }
    return lo;
}
__global__ void pool_concat_kernel(const __half* __restrict__ h2,
                                   const float* __restrict__ desc,
                                   const int* __restrict__ n2g,
                                   __half* __restrict__ X) {
    int g = blockIdx.x;
    __shared__ int s_lo, s_hi;
    if (threadIdx.x == 0) s_lo = lower_bound_dev(n2g, N_NODES, g);
    if (threadIdx.x == 1) s_hi = lower_bound_dev(n2g, N_NODES, g + 1);
    __syncthreads();
    int lo = s_lo, hi = s_hi;
    float inv = 1.f / fmaxf((float)(hi - lo), 1.f);
    int t = threadIdx.x;
    float2 a0 = make_float2(0.f, 0.f), a1 = make_float2(0.f, 0.f);
    for (int i = lo; i < hi; i++) {
        const __half2* row = reinterpret_cast<const __half2*>(
            h2 + (size_t)i * HID);
        float2 v0 = __half22float2(row[t * 2 + 0]);
        float2 v1 = __half22float2(row[t * 2 + 1]);
        a0.x += v0.x; a0.y += v0.y;
        a1.x += v1.x; a1.y += v1.y;
    }
    size_t rb = (size_t)g * XPAD;
    __half2* xrow = reinterpret_cast<__half2*>(X + rb);
    xrow[t * 2 + 0] = __floats2half2_rn(a0.x * inv, a0.y * inv);
    xrow[t * 2 + 1] = __floats2half2_rn(a1.x * inv, a1.y * inv);
    for (int d = t; d < N_DESC; d += 128)
        X[rb + HID + d] = __float2half_rn(desc[(size_t)g * N_DESC + d]);
    for (int d = t; d < XPAD - XDIM; d += 128)
        X[rb + XDIM + d] = __float2half_rn(0.f);
}

// ===========================================================================
// Tiny classifier
// ===========================================================================
__global__ void classifier_kernel(const float* __restrict__ m2,
                                  const float* __restrict__ cw,
                                  const float* __restrict__ cb,
                                  float* __restrict__ out) {
    int r = blockIdx.x * blockDim.x + threadIdx.x;
    if (r >= N_GRAPHS) return;
    float a0 = cb[0], a1 = cb[1];
    const float* row = m2 + (size_t)r * MLP2;
    #pragma unroll 4
    for (int k = 0; k < MLP2; k++) {
        float v = row[k];
        a0 += v * cw[k * 2 + 0];
        a1 += v * cw[k * 2 + 1];
    }
    out[r * 2 + 0] = a0;
    out[r * 2 + 1] = a1;
}

// ===========================================================================
// Launch  (order chosen so ncu -s 5 -c 1 captures gemm1, launch #6)
// ===========================================================================
extern "C" void kernel_launch(void* const* d_in, const int* in_sizes, int n_in,
                              void* d_out, int out_size) {
    const float* features    = (const float*)d_in[0];
    const float* descriptors = (const float*)d_in[1];
    const int*   src         = (const int*)  d_in[2];
    const int*   dst         = (const int*)  d_in[3];
    const int*   n2g         = (const int*)  d_in[4];
    const float* W1          = (const float*)d_in[5];
    const float* b1          = (const float*)d_in[6];
    const float* W2          = (const float*)d_in[7];
    const float* b2          = (const float*)d_in[8];
    const float* lw1         = (const float*)d_in[9];
    const float* lb1         = (const float*)d_in[10];
    const float* lw2         = (const float*)d_in[11];
    const float* lb2         = (const float*)d_in[12];
    const float* cw          = (const float*)d_in[13];
    const float* cb          = (const float*)d_in[14];
    float* out = (float*)d_out;

    __half *a0, *h1, *a1, *h2, *X;
    __half *B1hi, *B1lo, *B2hi, *B2lo, *BLhi, *BLlo;
    float *m1, *m2;
    cudaGetSymbolAddress((void**)&a0,   g_a0);
    cudaGetSymbolAddress((void**)&h1,   g_h1);
    cudaGetSymbolAddress((void**)&a1,   g_a1);
    cudaGetSymbolAddress((void**)&h2,   g_h2);
    cudaGetSymbolAddress((void**)&X,    g_X);
    cudaGetSymbolAddress((void**)&m1,   g_m1);
    cudaGetSymbolAddress((void**)&m2,   g_m2);
    cudaGetSymbolAddress((void**)&B1hi, g_B1hi);
    cudaGetSymbolAddress((void**)&B1lo, g_B1lo);
    cudaGetSymbolAddress((void**)&B2hi, g_B2hi);
    cudaGetSymbolAddress((void**)&B2lo, g_B2lo);
    cudaGetSymbolAddress((void**)&BLhi, g_BLhi);
    cudaGetSymbolAddress((void**)&BLlo, g_BLlo);

    cudaFuncSetAttribute(gemm_fp16_bsplit<true>,
                         cudaFuncAttributeMaxDynamicSharedMemorySize, GDSM);
    cudaFuncSetAttribute(gemm_fp16_bsplit<false>,
                         cudaFuncAttributeMaxDynamicSharedMemorySize, GDSM);

    // 1: fused zero + weight prep
    init_kernel<<<(INIT_TOTAL + 255) / 256, 256>>>(W1, W2, lw1,
                                                   B1hi, B1lo, B2hi, B2lo,
                                                   BLhi, BLlo);
    // 2-4: CSR build
    count_deg_kernel<<<(N_EDGES + 255) / 256, 256>>>(dst);
    scan_deg_kernel<<<1, 1024>>>();
    fill_csr_kernel<<<(N_EDGES + 255) / 256, 256>>>(src, dst);

    // 5: gather for layer 1
    gather_sum_128<<<N_NODES / 2, 256>>>(features, a0);

    // 6: GEMM1 (ncu-captured)
    { dim3 g(2, (N_NODES + 127) / 128);
      gemm_fp16_bsplit<true><<<g, 256, GDSM>>>(a0, B1hi, B1lo, b1, h1,
                                               N_NODES, HID, IN_DIM); }

    // 7-8: layer 2
    gather_sum_512h<<<N_NODES / 2, 256>>>(h1, a1);
    { dim3 g(2, (N_NODES + 127) / 128);
      gemm_fp16_bsplit<true><<<g, 256, GDSM>>>(a1, B2hi, B2lo, b2, h2,
                                               N_NODES, HID, HID); }

    // 9: pool + concat
    pool_concat_kernel<<<N_GRAPHS, 128>>>(h2, descriptors, n2g, X);

    // 10-12: MLP head
    { dim3 g(2, (N_GRAPHS + 127) / 128);
      gemm_fp16_bsplit<false><<<g, 256, GDSM>>>(X, BLhi, BLlo, lb1, m1,
                                                N_GRAPHS, MLP1, XPAD); }
    { dim3 g(1, (N_GRAPHS + 127) / 128);
      sgemm_bias_relu<<<g, 256>>>(m1, lw2, lb2, m2, N_GRAPHS, MLP2, MLP1, 1); }
    classifier_kernel<<<(N_GRAPHS + 127) / 128, 128>>>(m2, cw, cb, out);
}

// round 6
// speedup vs baseline: 4.2882x; 1.2427x over previous
#include <cuda_runtime.h>
#include <cuda_fp16.h>
#include <cstdint>
#include <cstddef>

// Problem constants
#define N_NODES  100000
#define N_EDGES  400000
#define N_GRAPHS 4000
#define IN_DIM   128
#define HID      512
#define N_DESC   200
#define XDIM     (HID + N_DESC)   // 712
#define XPAD     736              // multiple of 32
#define MLP1     500
#define MLP1PAD  512
#define MLP2     100

// ===========================================================================
// PTX helpers (plain sm_80-era features only)
// ===========================================================================
__device__ __forceinline__ uint32_t smem_to_u32(const void* p) {
    uint32_t a;
    asm("{ .reg .u64 t; cvta.to.shared.u64 t, %1; cvt.u32.u64 %0, t; }"
        : "=r"(a) : "l"(p));
    return a;
}
__device__ __forceinline__ void ldsm_x4(uint32_t& r0, uint32_t& r1,
                                        uint32_t& r2, uint32_t& r3,
                                        uint32_t addr) {
    asm volatile("ldmatrix.sync.aligned.m8n8.x4.shared.b16 {%0,%1,%2,%3}, [%4];"
                 : "=r"(r0), "=r"(r1), "=r"(r2), "=r"(r3) : "r"(addr));
}
__device__ __forceinline__ void mma_fp16(float* c, const uint32_t* a,
                                         uint32_t b0, uint32_t b1) {
    asm volatile(
        "mma.sync.aligned.m16n8k16.row.col.f32.f16.f16.f32 "
        "{%0,%1,%2,%3}, {%4,%5,%6,%7}, {%8,%9}, {%0,%1,%2,%3};"
        : "+f"(c[0]), "+f"(c[1]), "+f"(c[2]), "+f"(c[3])
        : "r"(a[0]), "r"(a[1]), "r"(a[2]), "r"(a[3]), "r"(b0), "r"(b1));
}
__device__ __forceinline__ void cpa16(uint32_t s, const void* g, uint32_t sz) {
    asm volatile("cp.async.cg.shared.global [%0], [%1], 16, %2;"
                 :: "r"(s), "l"(g), "r"(sz));
}
#define CP_COMMIT() asm volatile("cp.async.commit_group;" ::: "memory")
#define CP_WAIT(n)  asm volatile("cp.async.wait_group %0;" :: "n"(n) : "memory")

// ===========================================================================
// Device scratch (16B aligned for int4 access)
// ===========================================================================
__device__ __align__(16) int g_deg[N_NODES];
__device__ __align__(16) int g_off[N_NODES + 4];
__device__ __align__(16) int g_cur[N_NODES];
__device__ int g_csr[N_EDGES];

__device__ __half g_a0 [(size_t)N_NODES * IN_DIM];
__device__ __half g_h1 [(size_t)N_NODES * HID];
__device__ __half g_a1 [(size_t)N_NODES * HID];
__device__ __half g_h2 [(size_t)N_NODES * HID];
__device__ __half g_X  [(size_t)N_GRAPHS * XPAD];
__device__ float  g_m1 [(size_t)N_GRAPHS * MLP1];
__device__ float  g_m2 [(size_t)N_GRAPHS * MLP2];

// Weight images: B^T fp16, [Npad][Kpad], k-contiguous
__device__ __half g_B1[512 * 128];
__device__ __half g_B2[512 * 512];
__device__ __half g_BL[MLP1PAD * XPAD];

// ===========================================================================
// Fused init: zero g_deg + prep all three weight images (one launch)
// ===========================================================================
#define Z0 (N_NODES)
#define Z1 (512 * 128)
#define Z2 (512 * 512)
#define Z3 (MLP1PAD * XPAD)
#define INIT_TOTAL (Z0 + Z1 + Z2 + Z3)

__device__ __forceinline__ void prep_one(const float* __restrict__ W,
                                         __half* __restrict__ B,
                                         int local, int K_real, int N_real,
                                         int Kpad) {
    int n = local / Kpad, k = local % Kpad;
    float v = (k < K_real && n < N_real) ? W[(size_t)k * N_real + n] : 0.f;
    B[local] = __float2half_rn(v);
}

__global__ void init_kernel(const float* __restrict__ W1,
                            const float* __restrict__ W2,
                            const float* __restrict__ lw1,
                            __half* __restrict__ B1, __half* __restrict__ B2,
                            __half* __restrict__ BL) {
    int idx = blockIdx.x * blockDim.x + threadIdx.x;
    if (idx < Z0) {
        g_deg[idx] = 0;
    } else if (idx < Z0 + Z1) {
        prep_one(W1, B1, idx - Z0, IN_DIM, HID, 128);
    } else if (idx < Z0 + Z1 + Z2) {
        prep_one(W2, B2, idx - Z0 - Z1, HID, HID, 512);
    } else if (idx < INIT_TOTAL) {
        prep_one(lw1, BL, idx - Z0 - Z1 - Z2, XDIM, MLP1, XPAD);
    }
}

// ===========================================================================
// CSR construction
// ===========================================================================
__global__ void count_deg_kernel(const int* __restrict__ dst) {
    int e = blockIdx.x * blockDim.x + threadIdx.x;
    if (e < N_EDGES) atomicAdd(&g_deg[dst[e]], 1);
}

// Single-block scan, int4 loads/stores, fused cursor init.
__global__ void scan_deg_kernel() {
    __shared__ int part[1024];
    const int t = threadIdx.x;
    int s = 0;
    if (t < 1000) {
        const int4* p = reinterpret_cast<const int4*>(g_deg + t * 100);
        #pragma unroll
        for (int i = 0; i < 25; i++) {
            int4 v = p[i];
            s += v.x + v.y + v.z + v.w;
        }
    }
    part[t] = s;
    __syncthreads();
    for (int off = 1; off < 1024; off <<= 1) {
        int v = (t >= off) ? part[t - off] : 0;
        __syncthreads();
        part[t] += v;
        __syncthreads();
    }
    int run = (t == 0) ? 0 : part[t - 1];
    if (t < 1000) {
        const int4* p = reinterpret_cast<const int4*>(g_deg + t * 100);
        int4* o  = reinterpret_cast<int4*>(g_off + t * 100);
        int4* cu = reinterpret_cast<int4*>(g_cur + t * 100);
        #pragma unroll
        for (int i = 0; i < 25; i++) {
            int4 d = p[i];
            int4 w;
            w.x = run; run += d.x;
            w.y = run; run += d.y;
            w.z = run; run += d.z;
            w.w = run; run += d.w;
            o[i]  = w;
            cu[i] = w;
        }
    }
    if (t == 1023) g_off[N_NODES] = part[1023];
}

__global__ void fill_csr_kernel(const int* __restrict__ src,
                                const int* __restrict__ dst) {
    int e = blockIdx.x * blockDim.x + threadIdx.x;
    if (e < N_EDGES) {
        int p = atomicAdd(&g_cur[dst[e]], 1);
        g_csr[p] = src[e];
    }
}

// ===========================================================================
// Gather-sum kernels (2 nodes per 256-thread block)
// ===========================================================================
__global__ __launch_bounds__(256)
void gather_sum_128(const float* __restrict__ feat, __half* __restrict__ o) {
    int n = blockIdx.x * 2 + (threadIdx.x >> 7);
    int t = threadIdx.x & 127;
    int lo = g_off[n], hi = g_off[n + 1];
    float acc = 0.f;
    for (int j = lo; j < hi; j++)
        acc += feat[(size_t)g_csr[j] * IN_DIM + t];
    o[(size_t)n * IN_DIM + t] = __float2half_rn(acc);
}

__global__ __launch_bounds__(256)
void gather_sum_512h(const __half* __restrict__ h, __half* __restrict__ o) {
    int n = blockIdx.x * 2 + (threadIdx.x >> 7);
    int t = threadIdx.x & 127;
    int lo = g_off[n], hi = g_off[n + 1];
    float2 a0 = make_float2(0.f, 0.f), a1 = make_float2(0.f, 0.f);
    for (int j = lo; j < hi; j++) {
        const __half2* row = reinterpret_cast<const __half2*>(
            h + (size_t)g_csr[j] * HID);
        float2 v0 = __half22float2(row[t * 2 + 0]);
        float2 v1 = __half22float2(row[t * 2 + 1]);
        a0.x += v0.x; a0.y += v0.y;
        a1.x += v1.x; a1.y += v1.y;
    }
    __half2* orow = reinterpret_cast<__half2*>(o + (size_t)n * HID);
    orow[t * 2 + 0] = __floats2half2_rn(a0.x, a0.y);
    orow[t * 2 + 1] = __floats2half2_rn(a1.x, a1.y);
}

// ===========================================================================
// fp16 tensor-core GEMM (single pass): C[M,Nreal] = relu(A@W + bias)
// CTA tile 128m x 256n, BK=32, 8 warps (32m x 128n each), cp.async dbl-buffer.
// SMEM rows padded to 80B -> conflict-free ldmatrix.
// ===========================================================================
#define ATILE 10240u        // 128 rows * 80B
#define BTILE 20480u        // 256 rows * 80B
#define GBUF  30720u        // A + B
#define GDSM  (2 * GBUF)

template <bool HALF_OUT>
__global__ __launch_bounds__(256, 1)
void gemm_fp16(const __half* __restrict__ A, const __half* __restrict__ B,
               const float* __restrict__ bias, void* __restrict__ Cout,
               int M, int Nreal, int K)
{
    extern __shared__ char dsm[];
    const uint32_t sbase = smem_to_u32(dsm);
    const int tid  = threadIdx.x;
    const int lane = tid & 31;
    const int wid  = tid >> 5;
    const int row0 = blockIdx.y * 128;
    const int col0 = blockIdx.x * 256;
    const int NC   = K / 32;

    const int m_base = (wid & 3) * 32;
    const int n_base = (wid >> 2) * 128;

    float acc[2][16][4];
    #pragma unroll
    for (int i = 0; i < 2; i++)
        #pragma unroll
        for (int j = 0; j < 16; j++)
            #pragma unroll
            for (int q = 0; q < 4; q++) acc[i][j][q] = 0.f;

    auto load_chunk = [&](int buf, int c) {
        uint32_t s = sbase + (uint32_t)buf * GBUF;
        #pragma unroll
        for (int i = 0; i < 2; i++) {
            int f  = tid + i * 256;
            int m  = f >> 2, k8 = f & 3;
            int gm = row0 + m;
            uint32_t ok = (gm < M) ? 16u : 0u;
            int gmc = (gm < M) ? gm : 0;
            cpa16(s + m * 80 + k8 * 16, A + (size_t)gmc * K + c * 32 + k8 * 8, ok);
        }
        #pragma unroll
        for (int i = 0; i < 4; i++) {
            int f = tid + i * 256;
            int n = f >> 2, k8 = f & 3;
            size_t goff = (size_t)(col0 + n) * K + c * 32 + k8 * 8;
            cpa16(s + ATILE + n * 80 + k8 * 16, B + goff, 16u);
        }
        CP_COMMIT();
    };

    load_chunk(0, 0);

    for (int c = 0; c < NC; c++) {
        const int buf = c & 1;
        if (c + 1 < NC) {
            load_chunk(buf ^ 1, c + 1);
            CP_WAIT(1);
        } else {
            CP_WAIT(0);
        }
        __syncthreads();

        const uint32_t sA = sbase + (uint32_t)buf * GBUF;
        const uint32_t sB = sA + ATILE;

        #pragma unroll
        for (int ks = 0; ks < 2; ks++) {
            uint32_t a[2][4];
            #pragma unroll
            for (int im = 0; im < 2; im++) {
                uint32_t ra = sA + (uint32_t)(m_base + im * 16 + (lane & 15)) * 80
                                 + (uint32_t)(ks * 16 + ((lane >> 4) * 8)) * 2;
                ldsm_x4(a[im][0], a[im][1], a[im][2], a[im][3], ra);
            }
            #pragma unroll
            for (int g = 0; g < 8; g++) {
                uint32_t bh[4];
                uint32_t rb = sB + (uint32_t)(n_base + g * 16 +
                                   ((lane >> 4) & 1) * 8 + (lane & 7)) * 80
                                 + (uint32_t)(ks * 16 + ((lane >> 3) & 1) * 8) * 2;
                ldsm_x4(bh[0], bh[1], bh[2], bh[3], rb);
                #pragma unroll
                for (int im = 0; im < 2; im++) {
                    #pragma unroll
                    for (int sub = 0; sub < 2; sub++) {
                        mma_fp16(acc[im][g * 2 + sub], a[im],
                                 bh[sub * 2], bh[sub * 2 + 1]);
                    }
                }
            }
        }
        __syncthreads();
    }

    // ---- epilogue: bias + relu + store ----
    const bool full_n = (col0 + 256 <= Nreal);
    #pragma unroll
    for (int im = 0; im < 2; im++) {
        int m0 = row0 + m_base + im * 16 + (lane >> 2);
        #pragma unroll
        for (int j = 0; j < 16; j++) {
            int n = col0 + n_base + j * 8 + (lane & 3) * 2;
            if (full_n) {
                float b0 = bias[n], b1 = bias[n + 1];
                #pragma unroll
                for (int hr = 0; hr < 2; hr++) {
                    int mm = m0 + hr * 8;
                    if (mm >= M) continue;
                    float v0 = fmaxf(acc[im][j][hr * 2 + 0] + b0, 0.f);
                    float v1 = fmaxf(acc[im][j][hr * 2 + 1] + b1, 0.f);
                    if (HALF_OUT) {
                        *reinterpret_cast<__half2*>(
                            (__half*)Cout + (size_t)mm * Nreal + n) =
                            __floats2half2_rn(v0, v1);
                    } else {
                        *reinterpret_cast<float2*>(
                            (float*)Cout + (size_t)mm * Nreal + n) =
                            make_float2(v0, v1);
                    }
                }
            } else {
                #pragma unroll
                for (int q = 0; q < 4; q++) {
                    int mm = m0 + (q >> 1) * 8;
                    int nn = n + (q & 1);
                    if (mm < M && nn < Nreal) {
                        float v = fmaxf(acc[im][j][q] + bias[nn], 0.f);
                        if (HALF_OUT)
                            ((__half*)Cout)[(size_t)mm * Nreal + nn] =
                                __float2half_rn(v);
                        else
                            ((float*)Cout)[(size_t)mm * Nreal + nn] = v;
                    }
                }
            }
        }
    }
}

// ===========================================================================
// FFMA SGEMM (small MLP2 layer only, fp32)
// ===========================================================================
#define BM 128
#define BN 128
#define BK 8
#define TM 8
#define TN 8
__global__ __launch_bounds__(256)
void sgemm_bias_relu(const float* __restrict__ A, const float* __restrict__ B,
                     const float* __restrict__ bias, float* __restrict__ C,
                     int M, int N, int K, int relu) {
    __shared__ float As[BK][BM];
    __shared__ float Bs[BK][BN];
    const int tid  = threadIdx.x;
    const int row0 = blockIdx.y * BM;
    const int col0 = blockIdx.x * BN;
    const int tx = tid & 15;
    const int ty = tid >> 4;
    float acc[TM][TN];
    #pragma unroll
    for (int i = 0; i < TM; i++)
        #pragma unroll
        for (int j = 0; j < TN; j++) acc[i][j] = 0.f;
    for (int k0 = 0; k0 < K; k0 += BK) {
        #pragma unroll
        for (int i = 0; i < 4; i++) {
            int idx = tid + i * 256;
            int m = idx >> 3, k = idx & 7;
            int gm = row0 + m, gk = k0 + k;
            As[k][m] = (gm < M && gk < K) ? A[(size_t)gm * K + gk] : 0.f;
        }
        #pragma unroll
        for (int i = 0; i < 4; i++) {
            int idx = tid + i * 256;
            int k = idx >> 7, n = idx & 127;
            int gk = k0 + k, gn = col0 + n;
            Bs[k][n] = (gk < K && gn < N) ? B[(size_t)gk * N + gn] : 0.f;
        }
        __syncthreads();
        #pragma unroll
        for (int k = 0; k < BK; k++) {
            float a[TM], b[TN];
            #pragma unroll
            for (int i = 0; i < TM; i++) a[i] = As[k][ty * TM + i];
            #pragma unroll
            for (int j = 0; j < TN; j++) b[j] = Bs[k][tx * TN + j];
            #pragma unroll
            for (int i = 0; i < TM; i++)
                #pragma unroll
                for (int j = 0; j < TN; j++)
                    acc[i][j] += a[i] * b[j];
        }
        __syncthreads();
    }
    #pragma unroll
    for (int i = 0; i < TM; i++) {
        int gm = row0 + ty * TM + i;
        if (gm >= M) continue;
        #pragma unroll
        for (int j = 0; j < TN; j++) {
            int gn = col0 + tx * TN + j;
            if (gn >= N) continue;
            float v = acc[i][j] + (bias ? bias[gn] : 0.f);
            if (relu) v = fmaxf(v, 0.f);
            C[(size_t)gm * N + gn] = v;
        }
    }
}

// ===========================================================================
// Mean pool (sorted node2graph, fp16 input) + concat descriptors -> X fp16
// ===========================================================================
__device__ __forceinline__ int lower_bound_dev(const int* a, int n, int v) {
    int lo = 0, hi = n;
    while (lo < hi) {
        int m = (lo + hi) >> 1;
        if (a[m] < v) lo = m + 1; else hi = m;
    }
    return lo;
}
__global__ void pool_concat_kernel(const __half* __restrict__ h2,
                                   const float* __restrict__ desc,
                                   const int* __restrict__ n2g,
                                   __half* __restrict__ X) {
    int g = blockIdx.x;
    __shared__ int s_lo, s_hi;
    if (threadIdx.x == 0) s_lo = lower_bound_dev(n2g, N_NODES, g);
    if (threadIdx.x == 1) s_hi = lower_bound_dev(n2g, N_NODES, g + 1);
    __syncthreads();
    int lo = s_lo, hi = s_hi;
    float inv = 1.f / fmaxf((float)(hi - lo), 1.f);
    int t = threadIdx.x;
    float2 a0 = make_float2(0.f, 0.f), a1 = make_float2(0.f, 0.f);
    for (int i = lo; i < hi; i++) {
        const __half2* row = reinterpret_cast<const __half2*>(
            h2 + (size_t)i * HID);
        float2 v0 = __half22float2(row[t * 2 + 0]);
        float2 v1 = __half22float2(row[t * 2 + 1]);
        a0.x += v0.x; a0.y += v0.y;
        a1.x += v1.x; a1.y += v1.y;
    }
    size_t rb = (size_t)g * XPAD;
    __half2* xrow = reinterpret_cast<__half2*>(X + rb);
    xrow[t * 2 + 0] = __floats2half2_rn(a0.x * inv, a0.y * inv);
    xrow[t * 2 + 1] = __floats2half2_rn(a1.x * inv, a1.y * inv);
    for (int d = t; d < N_DESC; d += 128)
        X[rb + HID + d] = __float2half_rn(desc[(size_t)g * N_DESC + d]);
    for (int d = t; d < XPAD - XDIM; d += 128)
        X[rb + XDIM + d] = __float2half_rn(0.f);
}

// ===========================================================================
// Tiny classifier
// ===========================================================================
__global__ void classifier_kernel(const float* __restrict__ m2,
                                  const float* __restrict__ cw,
                                  const float* __restrict__ cb,
                                  float* __restrict__ out) {
    int r = blockIdx.x * blockDim.x + threadIdx.x;
    if (r >= N_GRAPHS) return;
    float a0 = cb[0], a1 = cb[1];
    const float* row = m2 + (size_t)r * MLP2;
    #pragma unroll 4
    for (int k = 0; k < MLP2; k++) {
        float v = row[k];
        a0 += v * cw[k * 2 + 0];
        a1 += v * cw[k * 2 + 1];
    }
    out[r * 2 + 0] = a0;
    out[r * 2 + 1] = a1;
}

// ===========================================================================
// Launch
// ===========================================================================
extern "C" void kernel_launch(void* const* d_in, const int* in_sizes, int n_in,
                              void* d_out, int out_size) {
    const float* features    = (const float*)d_in[0];
    const float* descriptors = (const float*)d_in[1];
    const int*   src         = (const int*)  d_in[2];
    const int*   dst         = (const int*)  d_in[3];
    const int*   n2g         = (const int*)  d_in[4];
    const float* W1          = (const float*)d_in[5];
    const float* b1          = (const float*)d_in[6];
    const float* W2          = (const float*)d_in[7];
    const float* b2          = (const float*)d_in[8];
    const float* lw1         = (const float*)d_in[9];
    const float* lb1         = (const float*)d_in[10];
    const float* lw2         = (const float*)d_in[11];
    const float* lb2         = (const float*)d_in[12];
    const float* cw          = (const float*)d_in[13];
    const float* cb          = (const float*)d_in[14];
    float* out = (float*)d_out;

    __half *a0, *h1, *a1, *h2, *X, *B1, *B2, *BL;
    float *m1, *m2;
    cudaGetSymbolAddress((void**)&a0, g_a0);
    cudaGetSymbolAddress((void**)&h1, g_h1);
    cudaGetSymbolAddress((void**)&a1, g_a1);
    cudaGetSymbolAddress((void**)&h2, g_h2);
    cudaGetSymbolAddress((void**)&X,  g_X);
    cudaGetSymbolAddress((void**)&m1, g_m1);
    cudaGetSymbolAddress((void**)&m2, g_m2);
    cudaGetSymbolAddress((void**)&B1, g_B1);
    cudaGetSymbolAddress((void**)&B2, g_B2);
    cudaGetSymbolAddress((void**)&BL, g_BL);

    cudaFuncSetAttribute(gemm_fp16<true>,
                         cudaFuncAttributeMaxDynamicSharedMemorySize, GDSM);
    cudaFuncSetAttribute(gemm_fp16<false>,
                         cudaFuncAttributeMaxDynamicSharedMemorySize, GDSM);

    // 1: fused zero + weight prep
    init_kernel<<<(INIT_TOTAL + 255) / 256, 256>>>(W1, W2, lw1, B1, B2, BL);
    // 2-4: CSR build
    count_deg_kernel<<<(N_EDGES + 255) / 256, 256>>>(dst);
    scan_deg_kernel<<<1, 1024>>>();
    fill_csr_kernel<<<(N_EDGES + 255) / 256, 256>>>(src, dst);

    // 5: gather for layer 1
    gather_sum_128<<<N_NODES / 2, 256>>>(features, a0);

    // 6: GEMM1
    { dim3 g(2, (N_NODES + 127) / 128);
      gemm_fp16<true><<<g, 256, GDSM>>>(a0, B1, b1, h1, N_NODES, HID, IN_DIM); }

    // 7-8: layer 2
    gather_sum_512h<<<N_NODES / 2, 256>>>(h1, a1);
    { dim3 g(2, (N_NODES + 127) / 128);
      gemm_fp16<true><<<g, 256, GDSM>>>(a1, B2, b2, h2, N_NODES, HID, HID); }

    // 9: pool + concat
    pool_concat_kernel<<<N_GRAPHS, 128>>>(h2, descriptors, n2g, X);

    // 10-12: MLP head
    { dim3 g(2, (N_GRAPHS + 127) / 128);
      gemm_fp16<false><<<g, 256, GDSM>>>(X, BL, lb1, m1, N_GRAPHS, MLP1, XPAD); }
    { dim3 g(1, (N_GRAPHS + 127) / 128);
      sgemm_bias_relu<<<g, 256>>>(m1, lw2, lb2, m2, N_GRAPHS, MLP2, MLP1, 1); }
    classifier_kernel<<<(N_GRAPHS + 127) / 128, 128>>>(m2, cw, cb, out);
}

// round 7
// speedup vs baseline: 5.9565x; 1.3890x over previous
#include <cuda_runtime.h>
#include <cuda_fp16.h>
#include <cstdint>
#include <cstddef>

// Problem constants
#define N_NODES  100000
#define N_EDGES  400000
#define N_GRAPHS 4000
#define IN_DIM   128
#define HID      512
#define N_DESC   200
#define XDIM     (HID + N_DESC)   // 712
#define XPAD     768              // multiple of 64 (BK)
#define MLP1     500
#define MLP1PAD  512
#define MLP2     100
#define NSCAN_BLOCKS ((N_NODES + 255) / 256)   // 391

// ===========================================================================
// PTX helpers (plain sm_80-era features only)
// ===========================================================================
__device__ __forceinline__ uint32_t smem_to_u32(const void* p) {
    uint32_t a;
    asm("{ .reg .u64 t; cvta.to.shared.u64 t, %1; cvt.u32.u64 %0, t; }"
        : "=r"(a) : "l"(p));
    return a;
}
__device__ __forceinline__ void ldsm_x4(uint32_t& r0, uint32_t& r1,
                                        uint32_t& r2, uint32_t& r3,
                                        uint32_t addr) {
    asm volatile("ldmatrix.sync.aligned.m8n8.x4.shared.b16 {%0,%1,%2,%3}, [%4];"
                 : "=r"(r0), "=r"(r1), "=r"(r2), "=r"(r3) : "r"(addr));
}
__device__ __forceinline__ void mma_fp16(float* c, const uint32_t* a,
                                         uint32_t b0, uint32_t b1) {
    asm volatile(
        "mma.sync.aligned.m16n8k16.row.col.f32.f16.f16.f32 "
        "{%0,%1,%2,%3}, {%4,%5,%6,%7}, {%8,%9}, {%0,%1,%2,%3};"
        : "+f"(c[0]), "+f"(c[1]), "+f"(c[2]), "+f"(c[3])
        : "r"(a[0]), "r"(a[1]), "r"(a[2]), "r"(a[3]), "r"(b0), "r"(b1));
}
__device__ __forceinline__ void cpa16(uint32_t s, const void* g, uint32_t sz) {
    asm volatile("cp.async.cg.shared.global [%0], [%1], 16, %2;"
                 :: "r"(s), "l"(g), "r"(sz));
}
#define CP_COMMIT() asm volatile("cp.async.commit_group;" ::: "memory")
#define CP_WAIT(n)  asm volatile("cp.async.wait_group %0;" :: "n"(n) : "memory")

// ===========================================================================
// Device scratch
// ===========================================================================
__device__ __align__(16) int g_deg[N_NODES];
__device__ __align__(16) int g_off[N_NODES + 4];
__device__ __align__(16) int g_cur[N_NODES];
__device__ int g_csr[N_EDGES];
__device__ int g_bsum[NSCAN_BLOCKS + 1];
__device__ int g_boff[NSCAN_BLOCKS + 1];

__device__ __half g_a0 [(size_t)N_NODES * IN_DIM];
__device__ __half g_h1 [(size_t)N_NODES * HID];
__device__ __half g_a1 [(size_t)N_NODES * HID];
__device__ __half g_h2 [(size_t)N_NODES * HID];
__device__ __half g_X  [(size_t)N_GRAPHS * XPAD];
__device__ float  g_m1 [(size_t)N_GRAPHS * MLP1];
__device__ float  g_m2 [(size_t)N_GRAPHS * MLP2];

// Weight images: B^T fp16, [Npad][Kpad], k-contiguous
__device__ __half g_B1[512 * 128];
__device__ __half g_B2[512 * 512];
__device__ __half g_BL[MLP1PAD * XPAD];

// ===========================================================================
// Fused init: zero g_deg + prep all three weight images
// ===========================================================================
#define Z0 (N_NODES)
#define Z1 (512 * 128)
#define Z2 (512 * 512)
#define Z3 (MLP1PAD * XPAD)
#define INIT_TOTAL (Z0 + Z1 + Z2 + Z3)

__device__ __forceinline__ void prep_one(const float* __restrict__ W,
                                         __half* __restrict__ B,
                                         int local, int K_real, int N_real,
                                         int Kpad) {
    int n = local / Kpad, k = local % Kpad;
    float v = (k < K_real && n < N_real) ? W[(size_t)k * N_real + n] : 0.f;
    B[local] = __float2half_rn(v);
}

__global__ void init_kernel(const float* __restrict__ W1,
                            const float* __restrict__ W2,
                            const float* __restrict__ lw1,
                            __half* __restrict__ B1, __half* __restrict__ B2,
                            __half* __restrict__ BL) {
    int idx = blockIdx.x * blockDim.x + threadIdx.x;
    if (idx < Z0) {
        g_deg[idx] = 0;
    } else if (idx < Z0 + Z1) {
        prep_one(W1, B1, idx - Z0, IN_DIM, HID, 128);
    } else if (idx < Z0 + Z1 + Z2) {
        prep_one(W2, B2, idx - Z0 - Z1, HID, HID, 512);
    } else if (idx < INIT_TOTAL) {
        prep_one(lw1, BL, idx - Z0 - Z1 - Z2, XDIM, MLP1, XPAD);
    }
}

// ===========================================================================
// CSR construction: count -> 3-phase scan -> fill
// ===========================================================================
__global__ void count_deg_kernel(const int* __restrict__ dst) {
    int e = blockIdx.x * blockDim.x + threadIdx.x;
    if (e < N_EDGES) atomicAdd(&g_deg[dst[e]], 1);
}

// Phase 1: per-block sums of 256 degrees
__global__ __launch_bounds__(256)
void scan_partial_kernel() {
    __shared__ int red[8];
    int i = blockIdx.x * 256 + threadIdx.x;
    int v = (i < N_NODES) ? g_deg[i] : 0;
    #pragma unroll
    for (int o = 16; o > 0; o >>= 1)
        v += __shfl_down_sync(0xFFFFFFFF, v, o);
    if ((threadIdx.x & 31) == 0) red[threadIdx.x >> 5] = v;
    __syncthreads();
    if (threadIdx.x < 8) {
        int s = red[threadIdx.x];
        #pragma unroll
        for (int o = 4; o > 0; o >>= 1)
            s += __shfl_down_sync(0xFF, s, o);
        if (threadIdx.x == 0) g_bsum[blockIdx.x] = s;
    }
}

// Phase 2: scan the 391 block sums (one small block)
__global__ void scan_blocks_kernel() {
    __shared__ int part[512];
    int t = threadIdx.x;
    part[t] = (t < NSCAN_BLOCKS) ? g_bsum[t] : 0;
    __syncthreads();
    for (int off = 1; off < 512; off <<= 1) {
        int v = (t >= off) ? part[t - off] : 0;
        __syncthreads();
        part[t] += v;
        __syncthreads();
    }
    if (t < NSCAN_BLOCKS) g_boff[t] = (t == 0) ? 0 : part[t - 1];
    if (t == NSCAN_BLOCKS) g_off[N_NODES] = part[NSCAN_BLOCKS - 1];
}

// Phase 3: intra-block exclusive scan + base offset, write g_off/g_cur
__global__ __launch_bounds__(256)
void scan_apply_kernel() {
    __shared__ int part[256];
    int t = threadIdx.x;
    int i = blockIdx.x * 256 + t;
    int d = (i < N_NODES) ? g_deg[i] : 0;
    part[t] = d;
    __syncthreads();
    for (int off = 1; off < 256; off <<= 1) {
        int v = (t >= off) ? part[t - off] : 0;
        __syncthreads();
        part[t] += v;
        __syncthreads();
    }
    if (i < N_NODES) {
        int off = g_boff[blockIdx.x] + part[t] - d;   // exclusive
        g_off[i] = off;
        g_cur[i] = off;
    }
}

__global__ void fill_csr_kernel(const int* __restrict__ src,
                                const int* __restrict__ dst) {
    int e = blockIdx.x * blockDim.x + threadIdx.x;
    if (e < N_EDGES) {
        int p = atomicAdd(&g_cur[dst[e]], 1);
        g_csr[p] = src[e];
    }
}

// ===========================================================================
// Gather-sum kernels: 16B loads
// ===========================================================================
// features fp32, row = 512B = 32 float4. 32 threads/node, 8 nodes/block.
__global__ __launch_bounds__(256)
void gather_sum_128(const float* __restrict__ feat, __half* __restrict__ o) {
    int n = blockIdx.x * 8 + (threadIdx.x >> 5);
    int t = threadIdx.x & 31;
    int lo = g_off[n], hi = g_off[n + 1];
    float4 acc = make_float4(0.f, 0.f, 0.f, 0.f);
    for (int j = lo; j < hi; j++) {
        float4 v = reinterpret_cast<const float4*>(
            feat + (size_t)g_csr[j] * IN_DIM)[t];
        acc.x += v.x; acc.y += v.y; acc.z += v.z; acc.w += v.w;
    }
    __half2 h0 = __floats2half2_rn(acc.x, acc.y);
    __half2 h1v = __floats2half2_rn(acc.z, acc.w);
    __half2* op = reinterpret_cast<__half2*>(o + (size_t)n * IN_DIM) + t * 2;
    op[0] = h0;
    op[1] = h1v;
}

// h fp16, row = 1KB = 64 uint4. 64 threads/node, 4 nodes/block.
__global__ __launch_bounds__(256)
void gather_sum_512h(const __half* __restrict__ h, __half* __restrict__ o) {
    int n = blockIdx.x * 4 + (threadIdx.x >> 6);
    int t = threadIdx.x & 63;
    int lo = g_off[n], hi = g_off[n + 1];
    float acc[8];
    #pragma unroll
    for (int i = 0; i < 8; i++) acc[i] = 0.f;
    for (int j = lo; j < hi; j++) {
        uint4 raw = reinterpret_cast<const uint4*>(
            h + (size_t)g_csr[j] * HID)[t];
        const __half2* hp = reinterpret_cast<const __half2*>(&raw);
        #pragma unroll
        for (int i = 0; i < 4; i++) {
            float2 v = __half22float2(hp[i]);
            acc[i * 2 + 0] += v.x;
            acc[i * 2 + 1] += v.y;
        }
    }
    uint4 out;
    __half2* op = reinterpret_cast<__half2*>(&out);
    #pragma unroll
    for (int i = 0; i < 4; i++)
        op[i] = __floats2half2_rn(acc[i * 2], acc[i * 2 + 1]);
    reinterpret_cast<uint4*>(o + (size_t)n * HID)[t] = out;
}

// ===========================================================================
// fp16 tensor-core GEMM: C[M,Nreal] = relu(A@W + bias)
// CTA tile 128m x 256n, BK=64, 8 warps (32m x 128n), cp.async double buffer.
// SMEM rows 144B (128B data + 16B pad) -> conflict-free ldmatrix.
// Epilogue staged through SMEM for fully-coalesced 16B stores (fp16 path).
// ===========================================================================
#define GROW  144u
#define ATILE 18432u        // 128 * 144
#define BTILE 36864u        // 256 * 144
#define GBUF  55296u        // A + B
#define GDSM  (2 * GBUF)
#define STG_STRIDE 528u     // fp16 stage row stride in bytes (264 halves)

template <bool HALF_OUT>
__global__ __launch_bounds__(256, 1)
void gemm_fp16(const __half* __restrict__ A, const __half* __restrict__ B,
               const float* __restrict__ bias, void* __restrict__ Cout,
               int M, int Nreal, int K)
{
    extern __shared__ char dsm[];
    const uint32_t sbase = smem_to_u32(dsm);
    const int tid  = threadIdx.x;
    const int lane = tid & 31;
    const int wid  = tid >> 5;
    const int row0 = blockIdx.y * 128;
    const int col0 = blockIdx.x * 256;
    const int NC   = K / 64;

    const int m_base = (wid & 3) * 32;
    const int n_base = (wid >> 2) * 128;

    float acc[2][16][4];
    #pragma unroll
    for (int i = 0; i < 2; i++)
        #pragma unroll
        for (int j = 0; j < 16; j++)
            #pragma unroll
            for (int q = 0; q < 4; q++) acc[i][j][q] = 0.f;

    auto load_chunk = [&](int buf, int c) {
        uint32_t s = sbase + (uint32_t)buf * GBUF;
        // A: 128 rows x 8 x 16B = 1024 units, 4/thread
        #pragma unroll
        for (int i = 0; i < 4; i++) {
            int f  = tid + i * 256;
            int m  = f >> 3, k8 = f & 7;
            int gm = row0 + m;
            uint32_t ok = (gm < M) ? 16u : 0u;
            int gmc = (gm < M) ? gm : 0;
            cpa16(s + m * GROW + k8 * 16,
                  A + (size_t)gmc * K + c * 64 + k8 * 8, ok);
        }
        // B: 256 rows x 8 x 16B = 2048 units, 8/thread
        #pragma unroll
        for (int i = 0; i < 8; i++) {
            int f = tid + i * 256;
            int n = f >> 3, k8 = f & 7;
            cpa16(s + ATILE + n * GROW + k8 * 16,
                  B + (size_t)(col0 + n) * K + c * 64 + k8 * 8, 16u);
        }
        CP_COMMIT();
    };

    load_chunk(0, 0);

    for (int c = 0; c < NC; c++) {
        const int buf = c & 1;
        if (c + 1 < NC) {
            load_chunk(buf ^ 1, c + 1);
            CP_WAIT(1);
        } else {
            CP_WAIT(0);
        }
        __syncthreads();

        const uint32_t sA = sbase + (uint32_t)buf * GBUF;
        const uint32_t sB = sA + ATILE;

        #pragma unroll
        for (int ks = 0; ks < 4; ks++) {
            uint32_t a[2][4];
            #pragma unroll
            for (int im = 0; im < 2; im++) {
                uint32_t ra = sA
                    + (uint32_t)(m_base + im * 16 + (lane & 15)) * GROW
                    + (uint32_t)(ks * 16 + ((lane >> 4) * 8)) * 2;
                ldsm_x4(a[im][0], a[im][1], a[im][2], a[im][3], ra);
            }
            #pragma unroll
            for (int g = 0; g < 8; g++) {
                uint32_t bh[4];
                uint32_t rb = sB
                    + (uint32_t)(n_base + g * 16 +
                                 ((lane >> 4) & 1) * 8 + (lane & 7)) * GROW
                    + (uint32_t)(ks * 16 + ((lane >> 3) & 1) * 8) * 2;
                ldsm_x4(bh[0], bh[1], bh[2], bh[3], rb);
                #pragma unroll
                for (int im = 0; im < 2; im++) {
                    #pragma unroll
                    for (int sub = 0; sub < 2; sub++) {
                        mma_fp16(acc[im][g * 2 + sub], a[im],
                                 bh[sub * 2], bh[sub * 2 + 1]);
                    }
                }
            }
        }
        __syncthreads();
    }

    // ---- epilogue ----
    const bool full_n = (col0 + 256 <= Nreal);
    if (HALF_OUT && full_n) {
        // Stage fp16 tile in smem (conflict-free 528B stride), then 16B stores
        #pragma unroll
        for (int im = 0; im < 2; im++) {
            int ml = m_base + im * 16 + (lane >> 2);
            #pragma unroll
            for (int j = 0; j < 16; j++) {
                int nl = n_base + j * 8 + (lane & 3) * 2;
                float b0 = bias[col0 + nl], b1 = bias[col0 + nl + 1];
                __half2* p0 = reinterpret_cast<__half2*>(
                    dsm + (uint32_t)ml * STG_STRIDE + nl * 2);
                *p0 = __floats2half2_rn(fmaxf(acc[im][j][0] + b0, 0.f),
                                        fmaxf(acc[im][j][1] + b1, 0.f));
                __half2* p1 = reinterpret_cast<__half2*>(
                    dsm + (uint32_t)(ml + 8) * STG_STRIDE + nl * 2);
                *p1 = __floats2half2_rn(fmaxf(acc[im][j][2] + b0, 0.f),
                                        fmaxf(acc[im][j][3] + b1, 0.f));
            }
        }
        __syncthreads();
        __half* C = (__half*)Cout;
        #pragma unroll
        for (int p = 0; p < 16; p++) {
            int idx = tid + p * 256;
            int r = idx >> 5, u = idx & 31;
            int gm = row0 + r;
            if (gm < M) {
                uint4 v = *reinterpret_cast<const uint4*>(
                    dsm + (uint32_t)r * STG_STRIDE + u * 16);
                *reinterpret_cast<uint4*>(
                    C + (size_t)gm * Nreal + col0 + u * 8) = v;
            }
        }
    } else {
        #pragma unroll
        for (int im = 0; im < 2; im++) {
            int m0 = row0 + m_base + im * 16 + (lane >> 2);
            #pragma unroll
            for (int j = 0; j < 16; j++) {
                int n = col0 + n_base + j * 8 + (lane & 3) * 2;
                #pragma unroll
                for (int q = 0; q < 4; q++) {
                    int mm = m0 + (q >> 1) * 8;
                    int nn = n + (q & 1);
                    if (mm < M && nn < Nreal) {
                        float v = fmaxf(acc[im][j][q] + bias[nn], 0.f);
                        if (HALF_OUT)
                            ((__half*)Cout)[(size_t)mm * Nreal + nn] =
                                __float2half_rn(v);
                        else
                            ((float*)Cout)[(size_t)mm * Nreal + nn] = v;
                    }
                }
            }
        }
    }
}

// ===========================================================================
// FFMA SGEMM (small MLP2 layer only, fp32)
// ===========================================================================
#define BM 128
#define BN 128
#define BK8 8
#define TM 8
#define TN 8
__global__ __launch_bounds__(256)
void sgemm_bias_relu(const float* __restrict__ A, const float* __restrict__ B,
                     const float* __restrict__ bias, float* __restrict__ C,
                     int M, int N, int K, int relu) {
    __shared__ float As[BK8][BM];
    __shared__ float Bs[BK8][BN];
    const int tid  = threadIdx.x;
    const int row0 = blockIdx.y * BM;
    const int col0 = blockIdx.x * BN;
    const int tx = tid & 15;
    const int ty = tid >> 4;
    float acc[TM][TN];
    #pragma unroll
    for (int i = 0; i < TM; i++)
        #pragma unroll
        for (int j = 0; j < TN; j++) acc[i][j] = 0.f;
    for (int k0 = 0; k0 < K; k0 += BK8) {
        #pragma unroll
        for (int i = 0; i < 4; i++) {
            int idx = tid + i * 256;
            int m = idx >> 3, k = idx & 7;
            int gm = row0 + m, gk = k0 + k;
            As[k][m] = (gm < M && gk < K) ? A[(size_t)gm * K + gk] : 0.f;
        }
        #pragma unroll
        for (int i = 0; i < 4; i++) {
            int idx = tid + i * 256;
            int k = idx >> 7, n = idx & 127;
            int gk = k0 + k, gn = col0 + n;
            Bs[k][n] = (gk < K && gn < N) ? B[(size_t)gk * N + gn] : 0.f;
        }
        __syncthreads();
        #pragma unroll
        for (int k = 0; k < BK8; k++) {
            float a[TM], b[TN];
            #pragma unroll
            for (int i = 0; i < TM; i++) a[i] = As[k][ty * TM + i];
            #pragma unroll
            for (int j = 0; j < TN; j++) b[j] = Bs[k][tx * TN + j];
            #pragma unroll
            for (int i = 0; i < TM; i++)
                #pragma unroll
                for (int j = 0; j < TN; j++)
                    acc[i][j] += a[i] * b[j];
        }
        __syncthreads();
    }
    #pragma unroll
    for (int i = 0; i < TM; i++) {
        int gm = row0 + ty * TM + i;
        if (gm >= M) continue;
        #pragma unroll
        for (int j = 0; j < TN; j++) {
            int gn = col0 + tx * TN + j;
            if (gn >= N) continue;
            float v = acc[i][j] + (bias ? bias[gn] : 0.f);
            if (relu) v = fmaxf(v, 0.f);
            C[(size_t)gm * N + gn] = v;
        }
    }
}

// ===========================================================================
// Mean pool (sorted node2graph, fp16 input) + concat descriptors -> X fp16
// ===========================================================================
__device__ __forceinline__ int lower_bound_dev(const int* a, int n, int v) {
    int lo = 0, hi = n;
    while (lo < hi) {
        int m = (lo + hi) >> 1;
        if (a[m] < v) lo = m + 1; else hi = m;
    }
    return lo;
}
__global__ void pool_concat_kernel(const __half* __restrict__ h2,
                                   const float* __restrict__ desc,
                                   const int* __restrict__ n2g,
                                   __half* __restrict__ X) {
    int g = blockIdx.x;
    __shared__ int s_lo, s_hi;
    if (threadIdx.x == 0) s_lo = lower_bound_dev(n2g, N_NODES, g);
    if (threadIdx.x == 1) s_hi = lower_bound_dev(n2g, N_NODES, g + 1);
    __syncthreads();
    int lo = s_lo, hi = s_hi;
    float inv = 1.f / fmaxf((float)(hi - lo), 1.f);
    int t = threadIdx.x;
    float2 a0 = make_float2(0.f, 0.f), a1 = make_float2(0.f, 0.f);
    for (int i = lo; i < hi; i++) {
        const __half2* row = reinterpret_cast<const __half2*>(
            h2 + (size_t)i * HID);
        float2 v0 = __half22float2(row[t * 2 + 0]);
        float2 v1 = __half22float2(row[t * 2 + 1]);
        a0.x += v0.x; a0.y += v0.y;
        a1.x += v1.x; a1.y += v1.y;
    }
    size_t rb = (size_t)g * XPAD;
    __half2* xrow = reinterpret_cast<__half2*>(X + rb);
    xrow[t * 2 + 0] = __floats2half2_rn(a0.x * inv, a0.y * inv);
    xrow[t * 2 + 1] = __floats2half2_rn(a1.x * inv, a1.y * inv);
    for (int d = t; d < N_DESC; d += 128)
        X[rb + HID + d] = __float2half_rn(desc[(size_t)g * N_DESC + d]);
    for (int d = t; d < XPAD - XDIM; d += 128)
        X[rb + XDIM + d] = __float2half_rn(0.f);
}

// ===========================================================================
// Tiny classifier
// ===========================================================================
__global__ void classifier_kernel(const float* __restrict__ m2,
                                  const float* __restrict__ cw,
                                  const float* __restrict__ cb,
                                  float* __restrict__ out) {
    int r = blockIdx.x * blockDim.x + threadIdx.x;
    if (r >= N_GRAPHS) return;
    float a0 = cb[0], a1 = cb[1];
    const float* row = m2 + (size_t)r * MLP2;
    #pragma unroll 4
    for (int k = 0; k < MLP2; k++) {
        float v = row[k];
        a0 += v * cw[k * 2 + 0];
        a1 += v * cw[k * 2 + 1];
    }
    out[r * 2 + 0] = a0;
    out[r * 2 + 1] = a1;
}

// ===========================================================================
// Launch
// ===========================================================================
extern "C" void kernel_launch(void* const* d_in, const int* in_sizes, int n_in,
                              void* d_out, int out_size) {
    const float* features    = (const float*)d_in[0];
    const float* descriptors = (const float*)d_in[1];
    const int*   src         = (const int*)  d_in[2];
    const int*   dst         = (const int*)  d_in[3];
    const int*   n2g         = (const int*)  d_in[4];
    const float* W1          = (const float*)d_in[5];
    const float* b1          = (const float*)d_in[6];
    const float* W2          = (const float*)d_in[7];
    const float* b2          = (const float*)d_in[8];
    const float* lw1         = (const float*)d_in[9];
    const float* lb1         = (const float*)d_in[10];
    const float* lw2         = (const float*)d_in[11];
    const float* lb2         = (const float*)d_in[12];
    const float* cw          = (const float*)d_in[13];
    const float* cb          = (const float*)d_in[14];
    float* out = (float*)d_out;

    __half *a0, *h1, *a1, *h2, *X, *B1, *B2, *BL;
    float *m1, *m2;
    cudaGetSymbolAddress((void**)&a0, g_a0);
    cudaGetSymbolAddress((void**)&h1, g_h1);
    cudaGetSymbolAddress((void**)&a1, g_a1);
    cudaGetSymbolAddress((void**)&h2, g_h2);
    cudaGetSymbolAddress((void**)&X,  g_X);
    cudaGetSymbolAddress((void**)&m1, g_m1);
    cudaGetSymbolAddress((void**)&m2, g_m2);
    cudaGetSymbolAddress((void**)&B1, g_B1);
    cudaGetSymbolAddress((void**)&B2, g_B2);
    cudaGetSymbolAddress((void**)&BL, g_BL);

    cudaFuncSetAttribute(gemm_fp16<true>,
                         cudaFuncAttributeMaxDynamicSharedMemorySize, GDSM);
    cudaFuncSetAttribute(gemm_fp16<false>,
                         cudaFuncAttributeMaxDynamicSharedMemorySize, GDSM);

    // init (zero deg + weight prep)
    init_kernel<<<(INIT_TOTAL + 255) / 256, 256>>>(W1, W2, lw1, B1, B2, BL);
    // CSR build
    count_deg_kernel<<<(N_EDGES + 255) / 256, 256>>>(dst);
    scan_partial_kernel<<<NSCAN_BLOCKS, 256>>>();
    scan_blocks_kernel<<<1, 512>>>();
    scan_apply_kernel<<<NSCAN_BLOCKS, 256>>>();
    fill_csr_kernel<<<(N_EDGES + 255) / 256, 256>>>(src, dst);

    // Layer 1
    gather_sum_128<<<N_NODES / 8, 256>>>(features, a0);
    { dim3 g(2, (N_NODES + 127) / 128);
      gemm_fp16<true><<<g, 256, GDSM>>>(a0, B1, b1, h1, N_NODES, HID, IN_DIM); }

    // Layer 2
    gather_sum_512h<<<N_NODES / 4, 256>>>(h1, a1);
    { dim3 g(2, (N_NODES + 127) / 128);
      gemm_fp16<true><<<g, 256, GDSM>>>(a1, B2, b2, h2, N_NODES, HID, HID); }

    // Pool + concat
    pool_concat_kernel<<<N_GRAPHS, 128>>>(h2, descriptors, n2g, X);

    // MLP head
    { dim3 g(2, (N_GRAPHS + 127) / 128);
      gemm_fp16<false><<<g, 256, GDSM>>>(X, BL, lb1, m1, N_GRAPHS, MLP1, XPAD); }
    { dim3 g(1, (N_GRAPHS + 127) / 128);
      sgemm_bias_relu<<<g, 256>>>(m1, lw2, lb2, m2, N_GRAPHS, MLP2, MLP1, 1); }
    classifier_kernel<<<(N_GRAPHS + 127) / 128, 128>>>(m2, cw, cb, out);
}